// round 5
// baseline (speedup 1.0000x reference)
#include <cuda_runtime.h>
#include <cuda_bf16.h>
#include <math.h>
#include <stdint.h>

#define CH 256
#define NBATCH 64
#define HW 1024
#define MTOT 65536
#define EPSV 1e-5f
#define T_ITERS 10
#define NCTA 64

// ---------------- device scratch ----------------
__device__ float g_mean[CH];
__device__ float g_msum[CH*NBATCH];
__device__ float g_bias[CH];
__device__ float g_Sig [CH*CH];
__device__ float g_SigN[CH*CH];
__device__ float g_P   [CH*CH];
__device__ float g_T1  [CH*CH];
__device__ float g_T2  [CH*CH];
__device__ float g_M   [CH*CH];
__device__ float g_part[192*16384];
__device__ __nv_bfloat16 g_xhi[64L*256*1024];
__device__ __nv_bfloat16 g_xlo[64L*256*1024];
__device__ __nv_bfloat16 g_Mhi[CH*CH];
__device__ __nv_bfloat16 g_Mlo[CH*CH];
__device__ volatile unsigned g_bar_cnt;

// ---------------- helpers ----------------
__device__ __forceinline__ uint32_t smem_u32(const void* p) {
    uint32_t a;
    asm("{ .reg .u64 t; cvta.to.shared.u64 t, %1; cvt.u32.u64 %0, t; }" : "=r"(a) : "l"(p));
    return a;
}
__device__ __forceinline__ float2 f2fma(float2 a, float2 b, float2 c) {
    union U { float2 f; unsigned long long u; };
    U ua, ub, uc, ud;
    ua.f = a; ub.f = b; uc.f = c;
    asm("fma.rn.f32x2 %0, %1, %2, %3;" : "=l"(ud.u) : "l"(ua.u), "l"(ub.u), "l"(uc.u));
    return ud.f;
}
__device__ __forceinline__ void ldm_x4(uint32_t* r, uint32_t addr) {
    asm volatile("ldmatrix.sync.aligned.m8n8.x4.shared.b16 {%0,%1,%2,%3}, [%4];"
        : "=r"(r[0]), "=r"(r[1]), "=r"(r[2]), "=r"(r[3]) : "r"(addr));
}
__device__ __forceinline__ void ldm_x2(uint32_t* r, uint32_t addr) {
    asm volatile("ldmatrix.sync.aligned.m8n8.x2.shared.b16 {%0,%1}, [%2];"
        : "=r"(r[0]), "=r"(r[1]) : "r"(addr));
}
__device__ __forceinline__ void ldm_x2t(uint32_t* r, uint32_t addr) {
    asm volatile("ldmatrix.sync.aligned.m8n8.x2.trans.shared.b16 {%0,%1}, [%2];"
        : "=r"(r[0]), "=r"(r[1]) : "r"(addr));
}
__device__ __forceinline__ void mma_bf16(float* c, const uint32_t* a, const uint32_t* b) {
    asm volatile("mma.sync.aligned.m16n8k16.row.col.f32.bf16.bf16.f32 "
        "{%0,%1,%2,%3}, {%4,%5,%6,%7}, {%8,%9}, {%0,%1,%2,%3};"
        : "+f"(c[0]), "+f"(c[1]), "+f"(c[2]), "+f"(c[3])
        : "r"(a[0]), "r"(a[1]), "r"(a[2]), "r"(a[3]), "r"(b[0]), "r"(b[1]));
}
__device__ __forceinline__ void cp16(uint32_t dst, const void* src) {
    asm volatile("cp.async.cg.shared.global [%0], [%1], 16;" :: "r"(dst), "l"(src));
}
__device__ __forceinline__ void cp_commit() { asm volatile("cp.async.commit_group;" ::: "memory"); }
template<int N> __device__ __forceinline__ void cp_wait() {
    asm volatile("cp.async.wait_group %0;" :: "n"(N) : "memory");
}

// ---------------- monotonic grid barrier (no resets, no races) ----------------
// Barrier k (1-based, tracked per-CTA in nbar) releases when g_bar_cnt >= k*NCTA.
// g_bar_cnt is zeroed by k_reset inside the graph before each solver run.
__global__ void k_reset() { g_bar_cnt = 0; }

struct GBar { unsigned nbar = 0; };
__device__ __forceinline__ void gbar(GBar& gb) {
    __syncthreads();
    if (threadIdx.x == 0) {
        __threadfence();
        unsigned target = (++gb.nbar) * NCTA;
        atomicAdd((unsigned*)&g_bar_cnt, 1u);
        while (g_bar_cnt < target) { }
        __threadfence();
    } else {
        ++gb.nbar;
    }
    __syncthreads();
}

// ---------------- convert X -> bf16 hi/lo + per-(c,n) sums ----------------
__global__ void __launch_bounds__(256) k_conv1(const float* __restrict__ X) {
    int c = blockIdx.x, n = blockIdx.y, t = threadIdx.x;
    size_t base = ((size_t)n*CH + c) * HW;
    float4 v = *(const float4*)(X + base + t*4);
    float f[4] = {v.x, v.y, v.z, v.w};
    __nv_bfloat16 h[4], l[4];
    #pragma unroll
    for (int k = 0; k < 4; k++) {
        h[k] = __float2bfloat16(f[k]);
        l[k] = __float2bfloat16(f[k] - __bfloat162float(h[k]));
    }
    __nv_bfloat162* ph = (__nv_bfloat162*)(g_xhi + base);
    __nv_bfloat162* pl = (__nv_bfloat162*)(g_xlo + base);
    ph[t*2]   = __nv_bfloat162(h[0], h[1]);
    ph[t*2+1] = __nv_bfloat162(h[2], h[3]);
    pl[t*2]   = __nv_bfloat162(l[0], l[1]);
    pl[t*2+1] = __nv_bfloat162(l[2], l[3]);
    float s = f[0] + f[1] + f[2] + f[3];
    __shared__ float sm[256];
    sm[t] = s; __syncthreads();
    for (int o = 128; o > 0; o >>= 1) { if (t < o) sm[t] += sm[t+o]; __syncthreads(); }
    if (t == 0) g_msum[c*NBATCH + n] = sm[0];
}

// ---------------- Gram: quadrants (0,0),(0,1),(1,1) x 64 n-splits, cp.async pipelined ----------------
#define GT 18432u                   // 128 rows * 144 B
#define GSTAGE (4u*GT)
#define GRAM_SMEM (2*GSTAGE)
__global__ void __launch_bounds__(256, 1) k_gram_mma() {
    extern __shared__ char sm[];
    int q = blockIdx.x, n = blockIdx.y;
    int ci0 = (q == 2) ? 128 : 0;
    int cj0 = (q == 0) ? 0 : 128;
    bool diag = (q != 1);
    int tid = threadIdx.x, lane = tid & 31, wid = tid >> 5;
    int wm = wid >> 2, wn = wid & 3;
    uint32_t sbase = smem_u32(sm);

    int rowL = tid >> 1, hL = tid & 1;
    const __nv_bfloat16* gAh = g_xhi + ((size_t)n*CH + ci0 + rowL)*HW + hL*32;
    const __nv_bfloat16* gAl = g_xlo + ((size_t)n*CH + ci0 + rowL)*HW + hL*32;
    const __nv_bfloat16* gBh = g_xhi + ((size_t)n*CH + cj0 + rowL)*HW + hL*32;
    const __nv_bfloat16* gBl = g_xlo + ((size_t)n*CH + cj0 + rowL)*HW + hL*32;

    float acc[4][4][4];
    #pragma unroll
    for (int a = 0; a < 4; a++)
        #pragma unroll
        for (int b = 0; b < 4; b++)
            #pragma unroll
            for (int k = 0; k < 4; k++) acc[a][b][k] = 0.f;

    auto prefetch = [&](int kb, int st) {
        uint32_t sb = sbase + st*GSTAGE;
        int pb = kb*64;
        uint32_t dA = sb + rowL*144 + hL*64;
        #pragma unroll
        for (int j = 0; j < 4; j++) {
            cp16(dA + j*16,      gAh + pb + j*8);
            cp16(dA + GT + j*16, gAl + pb + j*8);
        }
        if (!diag) {
            uint32_t dB = dA + 2*GT;
            #pragma unroll
            for (int j = 0; j < 4; j++) {
                cp16(dB + j*16,      gBh + pb + j*8);
                cp16(dB + GT + j*16, gBl + pb + j*8);
            }
        }
    };

    prefetch(0, 0); cp_commit();
    for (int kb = 0; kb < 16; kb++) {
        int cur = kb & 1;
        if (kb < 15) { prefetch(kb+1, cur^1); cp_commit(); cp_wait<1>(); }
        else         { cp_wait<0>(); }
        __syncthreads();
        uint32_t sb = sbase + cur*GSTAGE;
        uint32_t bb = sb + (diag ? 0 : 2*GT);
        #pragma unroll
        for (int ks = 0; ks < 4; ks++) {
            int k0 = ks*16;
            uint32_t ah[4][4], al[4][4], bh[4][2], bl[4][2];
            int ar = lane & 15, ac = (lane >> 4) * 8;
            #pragma unroll
            for (int mt = 0; mt < 4; mt++) {
                uint32_t ao = sb + (wm*64 + mt*16 + ar)*144 + (k0 + ac)*2;
                ldm_x4(ah[mt], ao);
                ldm_x4(al[mt], ao + GT);
            }
            int br = lane & 7, bc = ((lane >> 3) & 1) * 8;
            #pragma unroll
            for (int nt = 0; nt < 4; nt++) {
                uint32_t bo = bb + (wn*32 + nt*8 + br)*144 + (k0 + bc)*2;
                ldm_x2(bh[nt], bo);
                ldm_x2(bl[nt], bo + GT);
            }
            #pragma unroll
            for (int mt = 0; mt < 4; mt++)
                #pragma unroll
                for (int nt = 0; nt < 4; nt++) {
                    mma_bf16(acc[mt][nt], ah[mt], bh[nt]);
                    mma_bf16(acc[mt][nt], ah[mt], bl[nt]);
                    mma_bf16(acc[mt][nt], al[mt], bh[nt]);
                }
        }
        __syncthreads();
    }
    float* pout = g_part + ((size_t)q*64 + n)*16384;
    int rg = lane >> 2, cg = (lane & 3)*2;
    #pragma unroll
    for (int mt = 0; mt < 4; mt++)
        #pragma unroll
        for (int nt = 0; nt < 4; nt++) {
            int r0 = wm*64 + mt*16 + rg, c0 = wn*32 + nt*8 + cg;
            *(float2*)(pout + r0*128 + c0)     = make_float2(acc[mt][nt][0], acc[mt][nt][1]);
            *(float2*)(pout + (r0+8)*128 + c0) = make_float2(acc[mt][nt][2], acc[mt][nt][3]);
        }
}

// ---------------- 32x32 tile of 256^3 matmul (FFMA2), used by solver ----------------
__device__ __forceinline__ void mm_tile(float* __restrict__ Cm, const float* __restrict__ A,
                                        const float* __restrict__ B, int r0, int c0,
                                        int mode, float snorm) {
    __shared__ float As[32][33];
    __shared__ float Bs[32][36];
    int tid = threadIdx.x, tx = tid & 15, ty = tid >> 4;
    float2 acc0 = make_float2(0.f,0.f), acc1 = make_float2(0.f,0.f);
    for (int kb = 0; kb < 256; kb += 32) {
        int row = tid >> 3, fc = tid & 7;
        float4 v = __ldcg((const float4*)(A + (r0+row)*256 + kb + fc*4));
        As[row][fc*4+0]=v.x; As[row][fc*4+1]=v.y; As[row][fc*4+2]=v.z; As[row][fc*4+3]=v.w;
        float4 w = __ldcg((const float4*)(B + (kb+row)*256 + c0 + fc*4));
        *(float4*)(&Bs[row][fc*4]) = w;
        __syncthreads();
        #pragma unroll
        for (int k = 0; k < 32; k++) {
            float a0 = As[ty*2][k], a1 = As[ty*2+1][k];
            float2 b = *(float2*)(&Bs[k][tx*2]);
            acc0 = f2fma(make_float2(a0,a0), b, acc0);
            acc1 = f2fma(make_float2(a1,a1), b, acc1);
        }
        __syncthreads();
    }
    int r = r0 + ty*2, cc = c0 + tx*2;
    float2* o0 = (float2*)(Cm + r*256 + cc);
    float2* o1 = (float2*)(Cm + (r+1)*256 + cc);
    if (mode == 0) { *o0 = acc0; *o1 = acc1; }
    else if (mode == 1) {
        float2 d0 = __ldcg(o0), d1 = __ldcg(o1);
        *o0 = make_float2(1.5f*d0.x - 0.5f*acc0.x, 1.5f*d0.y - 0.5f*acc0.y);
        *o1 = make_float2(1.5f*d1.x - 0.5f*acc1.x, 1.5f*d1.y - 0.5f*acc1.y);
    } else {
        float2 v0 = make_float2(snorm*acc0.x, snorm*acc0.y);
        float2 v1 = make_float2(snorm*acc1.x, snorm*acc1.y);
        *o0 = v0; *o1 = v1;
        float f[4] = {v0.x, v0.y, v1.x, v1.y};
        int  off[4] = {r*256+cc, r*256+cc+1, (r+1)*256+cc, (r+1)*256+cc+1};
        #pragma unroll
        for (int k = 0; k < 4; k++) {
            __nv_bfloat16 h = __float2bfloat16(f[k]);
            g_Mhi[off[k]] = h;
            g_Mlo[off[k]] = __float2bfloat16(f[k] - __bfloat162float(h));
        }
    }
}

// ---------------- persistent solver: mean, Sigma, trace, Newton, M, bias ----------------
__global__ void __launch_bounds__(256) k_solver(const float* __restrict__ rot) {
    int cta = blockIdx.x, tid = threadIdx.x, lane = tid & 31, wid = tid >> 5;
    __shared__ float red[256];
    __shared__ float s_scal[2];
    GBar gb;

    // phase 0: mean reduce (one warp per channel)
    {
        int wg = cta*8 + wid;
        if (wg < 256) {
            float s = g_msum[wg*NBATCH + lane] + g_msum[wg*NBATCH + 32 + lane];
            #pragma unroll
            for (int o = 16; o > 0; o >>= 1) s += __shfl_xor_sync(~0u, s, o);
            if (lane == 0) g_mean[wg] = s * (1.f / (float)MTOT);
        }
    }
    gbar(gb);

    // phase 1: sigfin — each thread one (a, b..b+3)
    {
        int idx4 = cta*256 + tid;
        int a = idx4 >> 6, b = (idx4 & 63) * 4;
        float4 s4 = make_float4(0.f, 0.f, 0.f, 0.f);
        if (a < 128 || b >= 128) {
            int q = (a < 128) ? ((b < 128) ? 0 : 1) : 2;
            const float* pp = g_part + (size_t)q*64*16384 + (a & 127)*128 + (b & 127);
            #pragma unroll 4
            for (int t = 0; t < 64; t++) {
                float4 v = __ldcg((const float4*)(pp + (size_t)t*16384));
                s4.x += v.x; s4.y += v.y; s4.z += v.z; s4.w += v.w;
            }
        } else {
            const float* pp = g_part + (size_t)1*64*16384 + b*128 + (a - 128);
            #pragma unroll 4
            for (int t = 0; t < 64; t++) {
                const float* bb = pp + (size_t)t*16384;
                s4.x += __ldcg(bb); s4.y += __ldcg(bb+128); s4.z += __ldcg(bb+256); s4.w += __ldcg(bb+384);
            }
        }
        float ma = g_mean[a];
        float4 mb = *(const float4*)(g_mean + b);
        float4 v = make_float4(s4.x*(1.f/(float)MTOT) - ma*mb.x,
                               s4.y*(1.f/(float)MTOT) - ma*mb.y,
                               s4.z*(1.f/(float)MTOT) - ma*mb.z,
                               s4.w*(1.f/(float)MTOT) - ma*mb.w);
        if (a == b)   v.x += EPSV;
        if (a == b+1) v.y += EPSV;
        if (a == b+2) v.z += EPSV;
        if (a == b+3) v.w += EPSV;
        *(float4*)(g_Sig + a*256 + b) = v;
    }
    gbar(gb);

    // phase 2: trace (local per CTA) + init
    {
        red[tid] = __ldcg(g_Sig + tid*257);
        __syncthreads();
        for (int o = 128; o > 0; o >>= 1) { if (tid < o) red[tid] += red[tid+o]; __syncthreads(); }
        if (tid == 0) { float tr = red[0]; s_scal[0] = 1.f/tr; s_scal[1] = sqrtf(1.f/tr); }
        __syncthreads();
        float sc = s_scal[0];
        int base = cta*1024 + tid*4;
        float4 sg = __ldcg((const float4*)(g_Sig + base));
        *(float4*)(g_SigN + base) = make_float4(sg.x*sc, sg.y*sc, sg.z*sc, sg.w*sc);
        int r = base >> 8, c = base & 255;
        *(float4*)(g_P + base) = make_float4(r==c?1.f:0.f, r==c+1?1.f:0.f, r==c+2?1.f:0.f, r==c+3?1.f:0.f);
    }
    gbar(gb);

    // phase 3: Newton-Schulz, 2 grid phases per iteration
    int r0 = (cta >> 3) * 32, c0 = (cta & 7) * 32;
    for (int it = 0; it < T_ITERS; it++) {
        mm_tile(g_T1, g_P, g_P,    r0, c0, 0, 0.f);
        mm_tile(g_T2, g_P, g_SigN, r0, c0, 0, 0.f);
        gbar(gb);
        mm_tile(g_P, g_T1, g_T2, r0, c0, 1, 0.f);
        gbar(gb);
    }

    // phase 4: M = s * rot * P (+ bf16 split)
    mm_tile(g_M, rot, g_P, r0, c0, 2, s_scal[1]);
    gbar(gb);

    // phase 5: bias (one warp per output channel)
    {
        int wg = cta*8 + wid;
        if (wg < 256) {
            float s = 0.f;
            #pragma unroll
            for (int k = 0; k < 8; k++)
                s += __ldcg(g_M + wg*256 + lane + k*32) * g_mean[lane + k*32];
            #pragma unroll
            for (int o = 16; o > 0; o >>= 1) s += __shfl_xor_sync(~0u, s, o);
            if (lane == 0) g_bias[wg] = s;
        }
    }
}

// ---------------- output GEMM, cp.async pipelined ----------------
#define OAT 18432u                  // A tile: 128 rows * 144 B
#define OBT 17408u                  // B tile: 64 rows * 272 B
#define OBOFF (2u*OAT)
#define OSTAGE (2u*OAT + 2u*OBT)    // 71680
#define OUT_SMEM (2*OSTAGE)
__global__ void __launch_bounds__(256, 1) k_out_mma(float* __restrict__ out) {
    extern __shared__ char sm[];
    int p0 = blockIdx.x*128, d0 = blockIdx.y*128, n = blockIdx.z;
    int tid = threadIdx.x, lane = tid & 31, wid = tid >> 5;
    int wm = wid >> 2, wn = wid & 3;
    uint32_t sbase = smem_u32(sm);

    int rowA = tid >> 1, hA = tid & 1;
    int rowB = tid >> 2, qB = tid & 3;
    const __nv_bfloat16* gMh = g_Mhi + (d0 + rowA)*256 + hA*32;
    const __nv_bfloat16* gMl = g_Mlo + (d0 + rowA)*256 + hA*32;
    const __nv_bfloat16* gXh = g_xhi + ((size_t)n*CH + rowB)*HW + p0 + qB*32;
    const __nv_bfloat16* gXl = g_xlo + ((size_t)n*CH + rowB)*HW + p0 + qB*32;

    float acc[4][4][4];
    #pragma unroll
    for (int a = 0; a < 4; a++)
        #pragma unroll
        for (int b = 0; b < 4; b++)
            #pragma unroll
            for (int k = 0; k < 4; k++) acc[a][b][k] = 0.f;

    auto prefetch = [&](int cbi, int st) {
        uint32_t sb = sbase + st*OSTAGE;
        int cb = cbi*64;
        uint32_t dA = sb + rowA*144 + hA*64;
        #pragma unroll
        for (int j = 0; j < 4; j++) {
            cp16(dA + j*16,       gMh + cb + j*8);
            cp16(dA + OAT + j*16, gMl + cb + j*8);
        }
        uint32_t dB = sb + OBOFF + rowB*272 + qB*64;
        size_t go = (size_t)cb*HW;
        #pragma unroll
        for (int j = 0; j < 4; j++) {
            cp16(dB + j*16,       gXh + go + j*8);
            cp16(dB + OBT + j*16, gXl + go + j*8);
        }
    };

    prefetch(0, 0); cp_commit();
    for (int cbi = 0; cbi < 4; cbi++) {
        int cur = cbi & 1;
        if (cbi < 3) { prefetch(cbi+1, cur^1); cp_commit(); cp_wait<1>(); }
        else         { cp_wait<0>(); }
        __syncthreads();
        uint32_t sb = sbase + cur*OSTAGE;
        #pragma unroll
        for (int ks = 0; ks < 4; ks++) {
            int k0 = ks*16;
            uint32_t ah[4][4], al[4][4], bh[4][2], bl[4][2];
            int ar = lane & 15, ac = (lane >> 4) * 8;
            #pragma unroll
            for (int mt = 0; mt < 4; mt++) {
                uint32_t ao = sb + (wm*64 + mt*16 + ar)*144 + (k0 + ac)*2;
                ldm_x4(ah[mt], ao);
                ldm_x4(al[mt], ao + OAT);
            }
            int br = lane & 15;
            #pragma unroll
            for (int nt = 0; nt < 4; nt++) {
                uint32_t bo = sb + OBOFF + (k0 + br)*272 + (wn*32 + nt*8)*2;
                ldm_x2t(bh[nt], bo);
                ldm_x2t(bl[nt], bo + OBT);
            }
            #pragma unroll
            for (int mt = 0; mt < 4; mt++)
                #pragma unroll
                for (int nt = 0; nt < 4; nt++) {
                    mma_bf16(acc[mt][nt], ah[mt], bh[nt]);
                    mma_bf16(acc[mt][nt], ah[mt], bl[nt]);
                    mma_bf16(acc[mt][nt], al[mt], bh[nt]);
                }
        }
        __syncthreads();
    }
    float* On = out + (size_t)n * (CH*HW);
    int rg = lane >> 2, cg = (lane & 3)*2;
    #pragma unroll
    for (int mt = 0; mt < 4; mt++) {
        int d = d0 + wm*64 + mt*16 + rg;
        float b0 = g_bias[d], b1 = g_bias[d+8];
        #pragma unroll
        for (int nt = 0; nt < 4; nt++) {
            int p = p0 + wn*32 + nt*8 + cg;
            *(float2*)(On + (size_t)d*HW + p)     = make_float2(acc[mt][nt][0]-b0, acc[mt][nt][1]-b0);
            *(float2*)(On + (size_t)(d+8)*HW + p) = make_float2(acc[mt][nt][2]-b1, acc[mt][nt][3]-b1);
        }
    }
}

// ---------------- launch ----------------
extern "C" void kernel_launch(void* const* d_in, const int* in_sizes, int n_in,
                              void* d_out, int out_size) {
    const float* X   = (const float*)d_in[0];
    const float* rot = (const float*)d_in[1];
    if (n_in >= 2 && in_sizes[0] == CH*CH && in_sizes[1] != CH*CH) {
        X = (const float*)d_in[1]; rot = (const float*)d_in[0];
    }
    float* out = (float*)d_out;
    (void)out_size;

    cudaFuncSetAttribute(k_gram_mma, cudaFuncAttributeMaxDynamicSharedMemorySize, GRAM_SMEM);
    cudaFuncSetAttribute(k_out_mma,  cudaFuncAttributeMaxDynamicSharedMemorySize, OUT_SMEM);

    k_reset<<<1, 1>>>();
    k_conv1<<<dim3(256, 64), 256>>>(X);
    k_gram_mma<<<dim3(3, 64), 256, GRAM_SMEM>>>();
    k_solver<<<NCTA, 256>>>(rot);
    k_out_mma<<<dim3(8, 2, 64), 256, OUT_SMEM>>>(out);
}

// round 7
// speedup vs baseline: 1.0754x; 1.0754x over previous
#include <cuda_runtime.h>
#include <cuda_bf16.h>
#include <math.h>
#include <stdint.h>

#define CH 256
#define NBATCH 64
#define HW 1024
#define MTOT 65536
#define EPSV 1e-5f
#define T_ITERS 10
#define NCTA 64

// ---------------- device scratch (16B-aligned: float4 access everywhere) ----------------
__device__ float g_mean[CH];
__device__ float g_msum[CH*NBATCH];
__device__ float g_bias[CH];
__device__ float g_Sig [CH*CH];
__device__ float g_M   [CH*CH];
__device__ float g_part[192*16384];
__device__ __align__(16) __nv_bfloat16 g_xhi[64L*256*1024];
__device__ __align__(16) __nv_bfloat16 g_xlo[64L*256*1024];
__device__ __align__(16) __nv_bfloat16 g_Mhi [CH*CH], g_Mlo [CH*CH];
__device__ __align__(16) __nv_bfloat16 g_Phi [CH*CH], g_Plo [CH*CH];
__device__ __align__(16) __nv_bfloat16 g_T1hi[CH*CH], g_T1lo[CH*CH];
__device__ __align__(16) __nv_bfloat16 g_T2hi[CH*CH], g_T2lo[CH*CH];
__device__ __align__(16) __nv_bfloat16 g_SNhi[CH*CH], g_SNlo[CH*CH];
__device__ __align__(16) __nv_bfloat16 g_Rhi [CH*CH], g_Rlo [CH*CH];
__device__ volatile unsigned g_bar_cnt;

// ---------------- helpers ----------------
__device__ __forceinline__ uint32_t smem_u32(const void* p) {
    uint32_t a;
    asm("{ .reg .u64 t; cvta.to.shared.u64 t, %1; cvt.u32.u64 %0, t; }" : "=r"(a) : "l"(p));
    return a;
}
__device__ __forceinline__ void ldm_x4(uint32_t* r, uint32_t addr) {
    asm volatile("ldmatrix.sync.aligned.m8n8.x4.shared.b16 {%0,%1,%2,%3}, [%4];"
        : "=r"(r[0]), "=r"(r[1]), "=r"(r[2]), "=r"(r[3]) : "r"(addr));
}
__device__ __forceinline__ void ldm_x2(uint32_t* r, uint32_t addr) {
    asm volatile("ldmatrix.sync.aligned.m8n8.x2.shared.b16 {%0,%1}, [%2];"
        : "=r"(r[0]), "=r"(r[1]) : "r"(addr));
}
__device__ __forceinline__ void ldm_x2t(uint32_t* r, uint32_t addr) {
    asm volatile("ldmatrix.sync.aligned.m8n8.x2.trans.shared.b16 {%0,%1}, [%2];"
        : "=r"(r[0]), "=r"(r[1]) : "r"(addr));
}
__device__ __forceinline__ void mma_bf16(float* c, const uint32_t* a, const uint32_t* b) {
    asm volatile("mma.sync.aligned.m16n8k16.row.col.f32.bf16.bf16.f32 "
        "{%0,%1,%2,%3}, {%4,%5,%6,%7}, {%8,%9}, {%0,%1,%2,%3};"
        : "+f"(c[0]), "+f"(c[1]), "+f"(c[2]), "+f"(c[3])
        : "r"(a[0]), "r"(a[1]), "r"(a[2]), "r"(a[3]), "r"(b[0]), "r"(b[1]));
}
__device__ __forceinline__ void cp16(uint32_t dst, const void* src) {
    asm volatile("cp.async.cg.shared.global [%0], [%1], 16;" :: "r"(dst), "l"(src));
}
__device__ __forceinline__ void cp_commit() { asm volatile("cp.async.commit_group;" ::: "memory"); }
template<int N> __device__ __forceinline__ void cp_wait() {
    asm volatile("cp.async.wait_group %0;" :: "n"(N) : "memory");
}
__device__ __forceinline__ void bfsplit(float v, __nv_bfloat16& h, __nv_bfloat16& l) {
    h = __float2bfloat16(v);
    l = __float2bfloat16(v - __bfloat162float(h));
}

// ---------------- monotonic grid barrier ----------------
__global__ void k_reset() { g_bar_cnt = 0; }
struct GBar { unsigned nbar = 0; };
__device__ __forceinline__ void gbar(GBar& gb) {
    __syncthreads();
    if (threadIdx.x == 0) {
        __threadfence();
        unsigned target = (++gb.nbar) * NCTA;
        atomicAdd((unsigned*)&g_bar_cnt, 1u);
        while (g_bar_cnt < target) { __nanosleep(32); }
        __threadfence();
    } else {
        ++gb.nbar;
    }
    __syncthreads();
}

// ---------------- convert X -> bf16 hi/lo + per-(c,n) sums ----------------
__global__ void __launch_bounds__(256) k_conv1(const float* __restrict__ X) {
    int c = blockIdx.x, n = blockIdx.y, t = threadIdx.x;
    size_t base = ((size_t)n*CH + c) * HW;
    float4 v = *(const float4*)(X + base + t*4);
    float f[4] = {v.x, v.y, v.z, v.w};
    __nv_bfloat16 h[4], l[4];
    #pragma unroll
    for (int k = 0; k < 4; k++) bfsplit(f[k], h[k], l[k]);
    __nv_bfloat162* ph = (__nv_bfloat162*)(g_xhi + base);
    __nv_bfloat162* pl = (__nv_bfloat162*)(g_xlo + base);
    ph[t*2]   = __nv_bfloat162(h[0], h[1]);
    ph[t*2+1] = __nv_bfloat162(h[2], h[3]);
    pl[t*2]   = __nv_bfloat162(l[0], l[1]);
    pl[t*2+1] = __nv_bfloat162(l[2], l[3]);
    float s = f[0] + f[1] + f[2] + f[3];
    __shared__ float sm[256];
    sm[t] = s; __syncthreads();
    for (int o = 128; o > 0; o >>= 1) { if (t < o) sm[t] += sm[t+o]; __syncthreads(); }
    if (t == 0) g_msum[c*NBATCH + n] = sm[0];
}

// ---------------- Gram: quadrants (0,0),(0,1),(1,1) x 64 n-splits, cp.async pipelined ----------------
#define GT 18432u
#define GSTAGE (4u*GT)
#define GRAM_SMEM (2*GSTAGE)
__global__ void __launch_bounds__(256, 1) k_gram_mma() {
    extern __shared__ char sm[];
    int q = blockIdx.x, n = blockIdx.y;
    int ci0 = (q == 2) ? 128 : 0;
    int cj0 = (q == 0) ? 0 : 128;
    bool diag = (q != 1);
    int tid = threadIdx.x, lane = tid & 31, wid = tid >> 5;
    int wm = wid >> 2, wn = wid & 3;
    uint32_t sbase = smem_u32(sm);

    int rowL = tid >> 1, hL = tid & 1;
    const __nv_bfloat16* gAh = g_xhi + ((size_t)n*CH + ci0 + rowL)*HW + hL*32;
    const __nv_bfloat16* gAl = g_xlo + ((size_t)n*CH + ci0 + rowL)*HW + hL*32;
    const __nv_bfloat16* gBh = g_xhi + ((size_t)n*CH + cj0 + rowL)*HW + hL*32;
    const __nv_bfloat16* gBl = g_xlo + ((size_t)n*CH + cj0 + rowL)*HW + hL*32;

    float acc[4][4][4];
    #pragma unroll
    for (int a = 0; a < 4; a++)
        #pragma unroll
        for (int b = 0; b < 4; b++)
            #pragma unroll
            for (int k = 0; k < 4; k++) acc[a][b][k] = 0.f;

    auto prefetch = [&](int kb, int st) {
        uint32_t sb = sbase + st*GSTAGE;
        int pb = kb*64;
        uint32_t dA = sb + rowL*144 + hL*64;
        #pragma unroll
        for (int j = 0; j < 4; j++) {
            cp16(dA + j*16,      gAh + pb + j*8);
            cp16(dA + GT + j*16, gAl + pb + j*8);
        }
        if (!diag) {
            uint32_t dB = dA + 2*GT;
            #pragma unroll
            for (int j = 0; j < 4; j++) {
                cp16(dB + j*16,      gBh + pb + j*8);
                cp16(dB + GT + j*16, gBl + pb + j*8);
            }
        }
    };

    prefetch(0, 0); cp_commit();
    for (int kb = 0; kb < 16; kb++) {
        int cur = kb & 1;
        if (kb < 15) { prefetch(kb+1, cur^1); cp_commit(); cp_wait<1>(); }
        else         { cp_wait<0>(); }
        __syncthreads();
        uint32_t sb = sbase + cur*GSTAGE;
        uint32_t bb = sb + (diag ? 0 : 2*GT);
        #pragma unroll
        for (int ks = 0; ks < 4; ks++) {
            int k0 = ks*16;
            uint32_t ah[4][4], al[4][4], bh[4][2], bl[4][2];
            int ar = lane & 15, ac = (lane >> 4) * 8;
            #pragma unroll
            for (int mt = 0; mt < 4; mt++) {
                uint32_t ao = sb + (wm*64 + mt*16 + ar)*144 + (k0 + ac)*2;
                ldm_x4(ah[mt], ao);
                ldm_x4(al[mt], ao + GT);
            }
            int br = lane & 7, bc = ((lane >> 3) & 1) * 8;
            #pragma unroll
            for (int nt = 0; nt < 4; nt++) {
                uint32_t bo = bb + (wn*32 + nt*8 + br)*144 + (k0 + bc)*2;
                ldm_x2(bh[nt], bo);
                ldm_x2(bl[nt], bo + GT);
            }
            #pragma unroll
            for (int mt = 0; mt < 4; mt++)
                #pragma unroll
                for (int nt = 0; nt < 4; nt++) {
                    mma_bf16(acc[mt][nt], ah[mt], bh[nt]);
                    mma_bf16(acc[mt][nt], ah[mt], bl[nt]);
                    mma_bf16(acc[mt][nt], al[mt], bh[nt]);
                }
        }
        __syncthreads();
    }
    float* pout = g_part + ((size_t)q*64 + n)*16384;
    int rg = lane >> 2, cg = (lane & 3)*2;
    #pragma unroll
    for (int mt = 0; mt < 4; mt++)
        #pragma unroll
        for (int nt = 0; nt < 4; nt++) {
            int r0 = wm*64 + mt*16 + rg, c0 = wn*32 + nt*8 + cg;
            *(float2*)(pout + r0*128 + c0)     = make_float2(acc[mt][nt][0], acc[mt][nt][1]);
            *(float2*)(pout + (r0+8)*128 + c0) = make_float2(acc[mt][nt][2], acc[mt][nt][3]);
        }
}

// ---------------- tensor 64x64-tile matmul for the solver ----------------
#define NSM_ELE (4*64*72)
__device__ __forceinline__ void nt_mm(
    const __nv_bfloat16* __restrict__ Ah, const __nv_bfloat16* __restrict__ Al,
    const __nv_bfloat16* __restrict__ Bh, const __nv_bfloat16* __restrict__ Bl,
    __nv_bfloat16* __restrict__ Chi, __nv_bfloat16* __restrict__ Clo,
    int tile, int mode, float snorm, __nv_bfloat16* ns)
{
    int tr = (tile >> 2) * 64, tc = (tile & 3) * 64;
    int tid = threadIdx.x, lane = tid & 31, wid = tid >> 5;
    int wm = wid >> 1, wn = wid & 1;
    __nv_bfloat16* sAh = ns;
    __nv_bfloat16* sAl = ns + 64*72;
    __nv_bfloat16* sBh = ns + 2*64*72;
    __nv_bfloat16* sBl = ns + 3*64*72;
    uint32_t aAh = smem_u32(sAh), aAl = smem_u32(sAl);
    uint32_t aBh = smem_u32(sBh), aBl = smem_u32(sBl);

    float acc[4][4];
    #pragma unroll
    for (int nt = 0; nt < 4; nt++)
        #pragma unroll
        for (int k = 0; k < 4; k++) acc[nt][k] = 0.f;

    int lrow = tid >> 2, lcol = (tid & 3) * 16;   // 64 rows x 64 cols, 16 bf16 per thread
    for (int kb = 0; kb < 256; kb += 64) {
        __syncthreads();
        {
            const float4* pa_h = (const float4*)(Ah + (tr + lrow)*256 + kb + lcol);
            const float4* pa_l = (const float4*)(Al + (tr + lrow)*256 + kb + lcol);
            const float4* pb_h = (const float4*)(Bh + (kb + lrow)*256 + tc + lcol);
            const float4* pb_l = (const float4*)(Bl + (kb + lrow)*256 + tc + lcol);
            float4* da_h = (float4*)(sAh + lrow*72 + lcol);
            float4* da_l = (float4*)(sAl + lrow*72 + lcol);
            float4* db_h = (float4*)(sBh + lrow*72 + lcol);
            float4* db_l = (float4*)(sBl + lrow*72 + lcol);
            da_h[0] = pa_h[0]; da_h[1] = pa_h[1];
            da_l[0] = pa_l[0]; da_l[1] = pa_l[1];
            db_h[0] = pb_h[0]; db_h[1] = pb_h[1];
            db_l[0] = pb_l[0]; db_l[1] = pb_l[1];
        }
        __syncthreads();
        #pragma unroll
        for (int ks = 0; ks < 4; ks++) {
            int k0 = ks*16;
            uint32_t ah[4], al[4], bh[4][2], bl[4][2];
            int ar = lane & 15, ac = (lane >> 4) * 8;
            uint32_t ao = (wm*16 + ar)*144 + (k0 + ac)*2;
            ldm_x4(ah, aAh + ao);
            ldm_x4(al, aAl + ao);
            int br = lane & 15;
            #pragma unroll
            for (int nt = 0; nt < 4; nt++) {
                uint32_t bo = (k0 + br)*144 + (wn*32 + nt*8)*2;
                ldm_x2t(bh[nt], aBh + bo);
                ldm_x2t(bl[nt], aBl + bo);
            }
            #pragma unroll
            for (int nt = 0; nt < 4; nt++) {
                mma_bf16(acc[nt], ah, bh[nt]);
                mma_bf16(acc[nt], ah, bl[nt]);
                mma_bf16(acc[nt], al, bh[nt]);
            }
        }
    }
    __syncthreads();
    int rg = lane >> 2, cg = (lane & 3)*2;
    #pragma unroll
    for (int nt = 0; nt < 4; nt++) {
        int col = tc + wn*32 + nt*8 + cg;
        #pragma unroll
        for (int half = 0; half < 2; half++) {
            int row = tr + wm*16 + rg + half*8;
            float v0 = acc[nt][half*2], v1 = acc[nt][half*2+1];
            int idx = row*256 + col;
            if (mode == 1) {
                __nv_bfloat162 ph = *(__nv_bfloat162*)(g_Phi + idx);
                __nv_bfloat162 pl = *(__nv_bfloat162*)(g_Plo + idx);
                float p0 = __bfloat162float(ph.x) + __bfloat162float(pl.x);
                float p1 = __bfloat162float(ph.y) + __bfloat162float(pl.y);
                v0 = 1.5f*p0 - 0.5f*v0;
                v1 = 1.5f*p1 - 0.5f*v1;
            } else if (mode == 2) {
                v0 *= snorm; v1 *= snorm;
                *(float2*)(g_M + idx) = make_float2(v0, v1);
            }
            __nv_bfloat16 h0, l0, h1, l1;
            bfsplit(v0, h0, l0); bfsplit(v1, h1, l1);
            *(__nv_bfloat162*)(Chi + idx) = __nv_bfloat162(h0, h1);
            *(__nv_bfloat162*)(Clo + idx) = __nv_bfloat162(l0, l1);
        }
    }
}

// ---------------- persistent solver ----------------
__global__ void __launch_bounds__(256) k_solver(const float* __restrict__ rot) {
    int cta = blockIdx.x, tid = threadIdx.x, lane = tid & 31, wid = tid >> 5;
    __shared__ float red[256];
    __shared__ float s_scal[2];
    __shared__ __align__(16) __nv_bfloat16 nsm[NSM_ELE];
    GBar gb;

    // phase 0: mean reduce
    {
        int wg = cta*8 + wid;
        if (wg < 256) {
            float s = g_msum[wg*NBATCH + lane] + g_msum[wg*NBATCH + 32 + lane];
            #pragma unroll
            for (int o = 16; o > 0; o >>= 1) s += __shfl_xor_sync(~0u, s, o);
            if (lane == 0) g_mean[wg] = s * (1.f / (float)MTOT);
        }
    }
    gbar(gb);

    // phase 1: sigfin
    {
        int idx4 = cta*256 + tid;
        int a = idx4 >> 6, b = (idx4 & 63) * 4;
        float4 s4 = make_float4(0.f, 0.f, 0.f, 0.f);
        if (a < 128 || b >= 128) {
            int q = (a < 128) ? ((b < 128) ? 0 : 1) : 2;
            const float* pp = g_part + (size_t)q*64*16384 + (a & 127)*128 + (b & 127);
            #pragma unroll 4
            for (int t = 0; t < 64; t++) {
                float4 v = __ldcg((const float4*)(pp + (size_t)t*16384));
                s4.x += v.x; s4.y += v.y; s4.z += v.z; s4.w += v.w;
            }
        } else {
            const float* pp = g_part + (size_t)1*64*16384 + b*128 + (a - 128);
            #pragma unroll 4
            for (int t = 0; t < 64; t++) {
                const float* bb = pp + (size_t)t*16384;
                s4.x += __ldcg(bb); s4.y += __ldcg(bb+128); s4.z += __ldcg(bb+256); s4.w += __ldcg(bb+384);
            }
        }
        float ma = g_mean[a];
        float4 mb = *(const float4*)(g_mean + b);
        float4 v = make_float4(s4.x*(1.f/(float)MTOT) - ma*mb.x,
                               s4.y*(1.f/(float)MTOT) - ma*mb.y,
                               s4.z*(1.f/(float)MTOT) - ma*mb.z,
                               s4.w*(1.f/(float)MTOT) - ma*mb.w);
        if (a == b)   v.x += EPSV;
        if (a == b+1) v.y += EPSV;
        if (a == b+2) v.z += EPSV;
        if (a == b+3) v.w += EPSV;
        *(float4*)(g_Sig + a*256 + b) = v;
    }
    gbar(gb);

    // phase 2: trace + init SigN hi/lo, P = I hi/lo, rot hi/lo
    {
        red[tid] = __ldcg(g_Sig + tid*257);
        __syncthreads();
        for (int o = 128; o > 0; o >>= 1) { if (tid < o) red[tid] += red[tid+o]; __syncthreads(); }
        if (tid == 0) { float tr = red[0]; s_scal[0] = 1.f/tr; s_scal[1] = sqrtf(1.f/tr); }
        __syncthreads();
        float sc = s_scal[0];
        int base = cta*1024 + tid*4;
        float4 sg = __ldcg((const float4*)(g_Sig + base));
        float4 rr = __ldcg((const float4*)(rot + base));
        int r = base >> 8, c = base & 255;
        float sv[4] = {sg.x*sc, sg.y*sc, sg.z*sc, sg.w*sc};
        float rv[4] = {rr.x, rr.y, rr.z, rr.w};
        __nv_bfloat16 sh[4], sl[4], rh[4], rl[4], ph[4], pl[4];
        #pragma unroll
        for (int k = 0; k < 4; k++) {
            bfsplit(sv[k], sh[k], sl[k]);
            bfsplit(rv[k], rh[k], rl[k]);
            ph[k] = __float2bfloat16((r == c + k) ? 1.f : 0.f);
            pl[k] = __float2bfloat16(0.f);
        }
        *(__nv_bfloat162*)(g_SNhi + base)     = __nv_bfloat162(sh[0], sh[1]);
        *(__nv_bfloat162*)(g_SNhi + base + 2) = __nv_bfloat162(sh[2], sh[3]);
        *(__nv_bfloat162*)(g_SNlo + base)     = __nv_bfloat162(sl[0], sl[1]);
        *(__nv_bfloat162*)(g_SNlo + base + 2) = __nv_bfloat162(sl[2], sl[3]);
        *(__nv_bfloat162*)(g_Rhi + base)      = __nv_bfloat162(rh[0], rh[1]);
        *(__nv_bfloat162*)(g_Rhi + base + 2)  = __nv_bfloat162(rh[2], rh[3]);
        *(__nv_bfloat162*)(g_Rlo + base)      = __nv_bfloat162(rl[0], rl[1]);
        *(__nv_bfloat162*)(g_Rlo + base + 2)  = __nv_bfloat162(rl[2], rl[3]);
        *(__nv_bfloat162*)(g_Phi + base)      = __nv_bfloat162(ph[0], ph[1]);
        *(__nv_bfloat162*)(g_Phi + base + 2)  = __nv_bfloat162(ph[2], ph[3]);
        *(__nv_bfloat162*)(g_Plo + base)      = __nv_bfloat162(pl[0], pl[1]);
        *(__nv_bfloat162*)(g_Plo + base + 2)  = __nv_bfloat162(pl[2], pl[3]);
    }
    gbar(gb);

    // phase 3: Newton-Schulz on tensor cores (T1, T2 concurrent across CTAs)
    for (int it = 0; it < T_ITERS; it++) {
        if (cta < 16)
            nt_mm(g_Phi, g_Plo, g_Phi, g_Plo, g_T1hi, g_T1lo, cta, 0, 0.f, nsm);
        else if (cta < 32)
            nt_mm(g_Phi, g_Plo, g_SNhi, g_SNlo, g_T2hi, g_T2lo, cta - 16, 0, 0.f, nsm);
        gbar(gb);
        if (cta < 16)
            nt_mm(g_T1hi, g_T1lo, g_T2hi, g_T2lo, g_Phi, g_Plo, cta, 1, 0.f, nsm);
        gbar(gb);
    }

    // phase 4: M = s * rot * P
    if (cta < 16)
        nt_mm(g_Rhi, g_Rlo, g_Phi, g_Plo, g_Mhi, g_Mlo, cta, 2, s_scal[1], nsm);
    gbar(gb);

    // phase 5: bias
    {
        int wg = cta*8 + wid;
        if (wg < 256) {
            float s = 0.f;
            #pragma unroll
            for (int k = 0; k < 8; k++)
                s += __ldcg(g_M + wg*256 + lane + k*32) * g_mean[lane + k*32];
            #pragma unroll
            for (int o = 16; o > 0; o >>= 1) s += __shfl_xor_sync(~0u, s, o);
            if (lane == 0) g_bias[wg] = s;
        }
    }
}

// ---------------- output GEMM, cp.async pipelined ----------------
#define OAT 18432u
#define OBT 17408u
#define OBOFF (2u*OAT)
#define OSTAGE (2u*OAT + 2u*OBT)
#define OUT_SMEM (2*OSTAGE)
__global__ void __launch_bounds__(256, 1) k_out_mma(float* __restrict__ out) {
    extern __shared__ char sm[];
    int p0 = blockIdx.x*128, d0 = blockIdx.y*128, n = blockIdx.z;
    int tid = threadIdx.x, lane = tid & 31, wid = tid >> 5;
    int wm = wid >> 2, wn = wid & 3;
    uint32_t sbase = smem_u32(sm);

    int rowA = tid >> 1, hA = tid & 1;
    int rowB = tid >> 2, qB = tid & 3;
    const __nv_bfloat16* gMh = g_Mhi + (d0 + rowA)*256 + hA*32;
    const __nv_bfloat16* gMl = g_Mlo + (d0 + rowA)*256 + hA*32;
    const __nv_bfloat16* gXh = g_xhi + ((size_t)n*CH + rowB)*HW + p0 + qB*32;
    const __nv_bfloat16* gXl = g_xlo + ((size_t)n*CH + rowB)*HW + p0 + qB*32;

    float acc[4][4][4];
    #pragma unroll
    for (int a = 0; a < 4; a++)
        #pragma unroll
        for (int b = 0; b < 4; b++)
            #pragma unroll
            for (int k = 0; k < 4; k++) acc[a][b][k] = 0.f;

    auto prefetch = [&](int cbi, int st) {
        uint32_t sb = sbase + st*OSTAGE;
        int cb = cbi*64;
        uint32_t dA = sb + rowA*144 + hA*64;
        #pragma unroll
        for (int j = 0; j < 4; j++) {
            cp16(dA + j*16,       gMh + cb + j*8);
            cp16(dA + OAT + j*16, gMl + cb + j*8);
        }
        uint32_t dB = sb + OBOFF + rowB*272 + qB*64;
        size_t go = (size_t)cb*HW;
        #pragma unroll
        for (int j = 0; j < 4; j++) {
            cp16(dB + j*16,       gXh + go + j*8);
            cp16(dB + OBT + j*16, gXl + go + j*8);
        }
    };

    prefetch(0, 0); cp_commit();
    for (int cbi = 0; cbi < 4; cbi++) {
        int cur = cbi & 1;
        if (cbi < 3) { prefetch(cbi+1, cur^1); cp_commit(); cp_wait<1>(); }
        else         { cp_wait<0>(); }
        __syncthreads();
        uint32_t sb = sbase + cur*OSTAGE;
        #pragma unroll
        for (int ks = 0; ks < 4; ks++) {
            int k0 = ks*16;
            uint32_t ah[4][4], al[4][4], bh[4][2], bl[4][2];
            int ar = lane & 15, ac = (lane >> 4) * 8;
            #pragma unroll
            for (int mt = 0; mt < 4; mt++) {
                uint32_t ao = sb + (wm*64 + mt*16 + ar)*144 + (k0 + ac)*2;
                ldm_x4(ah[mt], ao);
                ldm_x4(al[mt], ao + OAT);
            }
            int br = lane & 15;
            #pragma unroll
            for (int nt = 0; nt < 4; nt++) {
                uint32_t bo = sb + OBOFF + (k0 + br)*272 + (wn*32 + nt*8)*2;
                ldm_x2t(bh[nt], bo);
                ldm_x2t(bl[nt], bo + OBT);
            }
            #pragma unroll
            for (int mt = 0; mt < 4; mt++)
                #pragma unroll
                for (int nt = 0; nt < 4; nt++) {
                    mma_bf16(acc[mt][nt], ah[mt], bh[nt]);
                    mma_bf16(acc[mt][nt], ah[mt], bl[nt]);
                    mma_bf16(acc[mt][nt], al[mt], bh[nt]);
                }
        }
        __syncthreads();
    }
    float* On = out + (size_t)n * (CH*HW);
    int rg = lane >> 2, cg = (lane & 3)*2;
    #pragma unroll
    for (int mt = 0; mt < 4; mt++) {
        int d = d0 + wm*64 + mt*16 + rg;
        float b0 = g_bias[d], b1 = g_bias[d+8];
        #pragma unroll
        for (int nt = 0; nt < 4; nt++) {
            int p = p0 + wn*32 + nt*8 + cg;
            *(float2*)(On + (size_t)d*HW + p)     = make_float2(acc[mt][nt][0]-b0, acc[mt][nt][1]-b0);
            *(float2*)(On + (size_t)(d+8)*HW + p) = make_float2(acc[mt][nt][2]-b1, acc[mt][nt][3]-b1);
        }
    }
}

// ---------------- launch ----------------
extern "C" void kernel_launch(void* const* d_in, const int* in_sizes, int n_in,
                              void* d_out, int out_size) {
    const float* X   = (const float*)d_in[0];
    const float* rot = (const float*)d_in[1];
    if (n_in >= 2 && in_sizes[0] == CH*CH && in_sizes[1] != CH*CH) {
        X = (const float*)d_in[1]; rot = (const float*)d_in[0];
    }
    float* out = (float*)d_out;
    (void)out_size;

    cudaFuncSetAttribute(k_gram_mma, cudaFuncAttributeMaxDynamicSharedMemorySize, GRAM_SMEM);
    cudaFuncSetAttribute(k_out_mma,  cudaFuncAttributeMaxDynamicSharedMemorySize, OUT_SMEM);

    k_reset<<<1, 1>>>();
    k_conv1<<<dim3(256, 64), 256>>>(X);
    k_gram_mma<<<dim3(3, 64), 256, GRAM_SMEM>>>();
    k_solver<<<NCTA, 256>>>(rot);
    k_out_mma<<<dim3(8, 2, 64), 256, OUT_SMEM>>>(out);
}

// round 8
// speedup vs baseline: 1.3442x; 1.2499x over previous
#include <cuda_runtime.h>
#include <cuda_bf16.h>
#include <math.h>
#include <stdint.h>

#define CH 256
#define NBATCH 64
#define HW 1024
#define MTOT 65536
#define EPSV 1e-5f
#define T_ITERS 10
#define NCTA 64

// ---------------- device scratch (16B-aligned: float4/cp.async access) ----------------
__device__ float g_mean[CH];
__device__ float g_msum[CH*NBATCH];
__device__ float g_bias[CH];
__device__ float g_Sig [CH*CH];
__device__ float g_M   [CH*CH];
__device__ float g_part[192*16384];
__device__ __align__(16) __nv_bfloat16 g_xhi[64L*256*1024];
__device__ __align__(16) __nv_bfloat16 g_xlo[64L*256*1024];
__device__ __align__(16) __nv_bfloat16 g_Mhi [CH*CH], g_Mlo [CH*CH];
__device__ __align__(16) __nv_bfloat16 g_Phi [CH*CH], g_Plo [CH*CH];
__device__ __align__(16) __nv_bfloat16 g_T1hi[CH*CH], g_T1lo[CH*CH];
__device__ __align__(16) __nv_bfloat16 g_T2hi[CH*CH], g_T2lo[CH*CH];
__device__ __align__(16) __nv_bfloat16 g_SNhi[CH*CH], g_SNlo[CH*CH];
__device__ __align__(16) __nv_bfloat16 g_Rhi [CH*CH], g_Rlo [CH*CH];
__device__ volatile unsigned g_bar_cnt;

// ---------------- helpers ----------------
__device__ __forceinline__ uint32_t smem_u32(const void* p) {
    uint32_t a;
    asm("{ .reg .u64 t; cvta.to.shared.u64 t, %1; cvt.u32.u64 %0, t; }" : "=r"(a) : "l"(p));
    return a;
}
__device__ __forceinline__ void ldm_x4(uint32_t* r, uint32_t addr) {
    asm volatile("ldmatrix.sync.aligned.m8n8.x4.shared.b16 {%0,%1,%2,%3}, [%4];"
        : "=r"(r[0]), "=r"(r[1]), "=r"(r[2]), "=r"(r[3]) : "r"(addr));
}
__device__ __forceinline__ void ldm_x2(uint32_t* r, uint32_t addr) {
    asm volatile("ldmatrix.sync.aligned.m8n8.x2.shared.b16 {%0,%1}, [%2];"
        : "=r"(r[0]), "=r"(r[1]) : "r"(addr));
}
__device__ __forceinline__ void ldm_x2t(uint32_t* r, uint32_t addr) {
    asm volatile("ldmatrix.sync.aligned.m8n8.x2.trans.shared.b16 {%0,%1}, [%2];"
        : "=r"(r[0]), "=r"(r[1]) : "r"(addr));
}
__device__ __forceinline__ void mma_bf16(float* c, const uint32_t* a, const uint32_t* b) {
    asm volatile("mma.sync.aligned.m16n8k16.row.col.f32.bf16.bf16.f32 "
        "{%0,%1,%2,%3}, {%4,%5,%6,%7}, {%8,%9}, {%0,%1,%2,%3};"
        : "+f"(c[0]), "+f"(c[1]), "+f"(c[2]), "+f"(c[3])
        : "r"(a[0]), "r"(a[1]), "r"(a[2]), "r"(a[3]), "r"(b[0]), "r"(b[1]));
}
__device__ __forceinline__ void cp16(uint32_t dst, const void* src) {
    asm volatile("cp.async.cg.shared.global [%0], [%1], 16;" :: "r"(dst), "l"(src));
}
__device__ __forceinline__ void cp_commit() { asm volatile("cp.async.commit_group;" ::: "memory"); }
template<int N> __device__ __forceinline__ void cp_wait() {
    asm volatile("cp.async.wait_group %0;" :: "n"(N) : "memory");
}
__device__ __forceinline__ void bfsplit(float v, __nv_bfloat16& h, __nv_bfloat16& l) {
    h = __float2bfloat16(v);
    l = __float2bfloat16(v - __bfloat162float(h));
}

// ---------------- monotonic grid barrier ----------------
__global__ void k_reset() { g_bar_cnt = 0; }
struct GBar { unsigned nbar = 0; };
__device__ __forceinline__ void gbar(GBar& gb) {
    __syncthreads();
    if (threadIdx.x == 0) {
        __threadfence();
        unsigned target = (++gb.nbar) * NCTA;
        atomicAdd((unsigned*)&g_bar_cnt, 1u);
        while (g_bar_cnt < target) { __nanosleep(32); }
        __threadfence();
    } else {
        ++gb.nbar;
    }
    __syncthreads();
}

// ---------------- convert X -> bf16 hi/lo + per-(c,n) sums ----------------
__global__ void __launch_bounds__(256) k_conv1(const float* __restrict__ X) {
    int c = blockIdx.x, n = blockIdx.y, t = threadIdx.x;
    size_t base = ((size_t)n*CH + c) * HW;
    float4 v = *(const float4*)(X + base + t*4);
    float f[4] = {v.x, v.y, v.z, v.w};
    __nv_bfloat16 h[4], l[4];
    #pragma unroll
    for (int k = 0; k < 4; k++) bfsplit(f[k], h[k], l[k]);
    __nv_bfloat162* ph = (__nv_bfloat162*)(g_xhi + base);
    __nv_bfloat162* pl = (__nv_bfloat162*)(g_xlo + base);
    ph[t*2]   = __nv_bfloat162(h[0], h[1]);
    ph[t*2+1] = __nv_bfloat162(h[2], h[3]);
    pl[t*2]   = __nv_bfloat162(l[0], l[1]);
    pl[t*2+1] = __nv_bfloat162(l[2], l[3]);
    float s = f[0] + f[1] + f[2] + f[3];
    __shared__ float sm[256];
    sm[t] = s; __syncthreads();
    for (int o = 128; o > 0; o >>= 1) { if (t < o) sm[t] += sm[t+o]; __syncthreads(); }
    if (t == 0) g_msum[c*NBATCH + n] = sm[0];
}

// ---------------- Gram: quadrants (0,0),(0,1),(1,1) x 64 n-splits, cp.async pipelined ----------------
#define GT 18432u
#define GSTAGE (4u*GT)
#define GRAM_SMEM (2*GSTAGE)
__global__ void __launch_bounds__(256, 1) k_gram_mma() {
    extern __shared__ char sm[];
    int q = blockIdx.x, n = blockIdx.y;
    int ci0 = (q == 2) ? 128 : 0;
    int cj0 = (q == 0) ? 0 : 128;
    bool diag = (q != 1);
    int tid = threadIdx.x, lane = tid & 31, wid = tid >> 5;
    int wm = wid >> 2, wn = wid & 3;
    uint32_t sbase = smem_u32(sm);

    int rowL = tid >> 1, hL = tid & 1;
    const __nv_bfloat16* gAh = g_xhi + ((size_t)n*CH + ci0 + rowL)*HW + hL*32;
    const __nv_bfloat16* gAl = g_xlo + ((size_t)n*CH + ci0 + rowL)*HW + hL*32;
    const __nv_bfloat16* gBh = g_xhi + ((size_t)n*CH + cj0 + rowL)*HW + hL*32;
    const __nv_bfloat16* gBl = g_xlo + ((size_t)n*CH + cj0 + rowL)*HW + hL*32;

    float acc[4][4][4];
    #pragma unroll
    for (int a = 0; a < 4; a++)
        #pragma unroll
        for (int b = 0; b < 4; b++)
            #pragma unroll
            for (int k = 0; k < 4; k++) acc[a][b][k] = 0.f;

    auto prefetch = [&](int kb, int st) {
        uint32_t sb = sbase + st*GSTAGE;
        int pb = kb*64;
        uint32_t dA = sb + rowL*144 + hL*64;
        #pragma unroll
        for (int j = 0; j < 4; j++) {
            cp16(dA + j*16,      gAh + pb + j*8);
            cp16(dA + GT + j*16, gAl + pb + j*8);
        }
        if (!diag) {
            uint32_t dB = dA + 2*GT;
            #pragma unroll
            for (int j = 0; j < 4; j++) {
                cp16(dB + j*16,      gBh + pb + j*8);
                cp16(dB + GT + j*16, gBl + pb + j*8);
            }
        }
    };

    prefetch(0, 0); cp_commit();
    for (int kb = 0; kb < 16; kb++) {
        int cur = kb & 1;
        if (kb < 15) { prefetch(kb+1, cur^1); cp_commit(); cp_wait<1>(); }
        else         { cp_wait<0>(); }
        __syncthreads();
        uint32_t sb = sbase + cur*GSTAGE;
        uint32_t bb = sb + (diag ? 0 : 2*GT);
        #pragma unroll
        for (int ks = 0; ks < 4; ks++) {
            int k0 = ks*16;
            uint32_t ah[4][4], al[4][4], bh[4][2], bl[4][2];
            int ar = lane & 15, ac = (lane >> 4) * 8;
            #pragma unroll
            for (int mt = 0; mt < 4; mt++) {
                uint32_t ao = sb + (wm*64 + mt*16 + ar)*144 + (k0 + ac)*2;
                ldm_x4(ah[mt], ao);
                ldm_x4(al[mt], ao + GT);
            }
            int br = lane & 7, bc = ((lane >> 3) & 1) * 8;
            #pragma unroll
            for (int nt = 0; nt < 4; nt++) {
                uint32_t bo = bb + (wn*32 + nt*8 + br)*144 + (k0 + bc)*2;
                ldm_x2(bh[nt], bo);
                ldm_x2(bl[nt], bo + GT);
            }
            #pragma unroll
            for (int mt = 0; mt < 4; mt++)
                #pragma unroll
                for (int nt = 0; nt < 4; nt++) {
                    mma_bf16(acc[mt][nt], ah[mt], bh[nt]);
                    mma_bf16(acc[mt][nt], ah[mt], bl[nt]);
                    mma_bf16(acc[mt][nt], al[mt], bh[nt]);
                }
        }
        __syncthreads();
    }
    float* pout = g_part + ((size_t)q*64 + n)*16384;
    int rg = lane >> 2, cg = (lane & 3)*2;
    #pragma unroll
    for (int mt = 0; mt < 4; mt++)
        #pragma unroll
        for (int nt = 0; nt < 4; nt++) {
            int r0 = wm*64 + mt*16 + rg, c0 = wn*32 + nt*8 + cg;
            *(float2*)(pout + r0*128 + c0)     = make_float2(acc[mt][nt][0], acc[mt][nt][1]);
            *(float2*)(pout + (r0+8)*128 + c0) = make_float2(acc[mt][nt][2], acc[mt][nt][3]);
        }
}

// ---------------- pipelined tensor tile matmul for the solver ----------------
// TM x 32 output tile, K=256 in 4 chunks of 64, cp.async double-buffered.
// TM=64: warps 4(m) x 2(n), warp tile 16x16. TM=32: warps 2(m) x 4(n), warp tile 16x8.
template<int TM>
__device__ __forceinline__ void nt_mm2(
    const __nv_bfloat16* __restrict__ Ah, const __nv_bfloat16* __restrict__ Al,
    const __nv_bfloat16* __restrict__ Bh, const __nv_bfloat16* __restrict__ Bl,
    __nv_bfloat16* __restrict__ Chi, __nv_bfloat16* __restrict__ Clo,
    int tr, int tc, int mode, float snorm, __nv_bfloat16* ns)
{
    constexpr int SA  = TM*72;         // bf16 elems per A tile (stride 72)
    constexpr int SB  = 64*40;         // bf16 elems per B tile (stride 40)
    constexpr int ST  = 2*SA + 2*SB;   // per stage
    constexpr int NT  = (TM == 64) ? 2 : 1;
    constexpr int WNW = (TM == 64) ? 16 : 8;
    int tid = threadIdx.x, lane = tid & 31, wid = tid >> 5;
    int wm = (TM == 64) ? (wid >> 1) : (wid >> 2);
    int wn = (TM == 64) ? (wid & 1)  : (wid & 3);
    uint32_t base = smem_u32(ns);

    float acc[NT][4];
    #pragma unroll
    for (int nt = 0; nt < NT; nt++)
        #pragma unroll
        for (int k = 0; k < 4; k++) acc[nt][k] = 0.f;

    int brow = tid >> 2, bcol = tid & 3;

    auto stage = [&](int kb, int st) {
        uint32_t sb = base + st*(ST*2);
        #pragma unroll
        for (int c = 0; c < TM*8; c += 256) {
            int cc = c + tid;
            int row = cc >> 3, col = cc & 7;
            uint32_t d = sb + row*144 + col*16;
            cp16(d,        Ah + (tr + row)*256 + kb + col*8);
            cp16(d + SA*2, Al + (tr + row)*256 + kb + col*8);
        }
        uint32_t dB = sb + 2*(SA*2) + brow*80 + bcol*16;
        cp16(dB,        Bh + (kb + brow)*256 + tc + bcol*8);
        cp16(dB + SB*2, Bl + (kb + brow)*256 + tc + bcol*8);
    };

    stage(0, 0); cp_commit();
    for (int kb = 0; kb < 4; kb++) {
        int cur = kb & 1;
        if (kb < 3) { stage((kb+1)*64, cur^1); cp_commit(); cp_wait<1>(); }
        else        { cp_wait<0>(); }
        __syncthreads();
        uint32_t sb  = base + cur*(ST*2);
        uint32_t sbB = sb + 2*(SA*2);
        #pragma unroll
        for (int ks = 0; ks < 4; ks++) {
            int k0 = ks*16;
            uint32_t ah[4], al[4], bh[NT][2], bl[NT][2];
            uint32_t ao = sb + (wm*16 + (lane & 15))*144 + (k0 + (lane >> 4)*8)*2;
            ldm_x4(ah, ao);
            ldm_x4(al, ao + SA*2);
            #pragma unroll
            for (int nt = 0; nt < NT; nt++) {
                uint32_t bo = sbB + (k0 + (lane & 15))*80 + (wn*WNW + nt*8)*2;
                ldm_x2t(bh[nt], bo);
                ldm_x2t(bl[nt], bo + SB*2);
            }
            #pragma unroll
            for (int nt = 0; nt < NT; nt++) {
                mma_bf16(acc[nt], ah, bh[nt]);
                mma_bf16(acc[nt], ah, bl[nt]);
                mma_bf16(acc[nt], al, bh[nt]);
            }
        }
        __syncthreads();
    }
    int rg = lane >> 2, cg = (lane & 3)*2;
    #pragma unroll
    for (int nt = 0; nt < NT; nt++) {
        int col = tc + wn*WNW + nt*8 + cg;
        #pragma unroll
        for (int half = 0; half < 2; half++) {
            int row = tr + wm*16 + rg + half*8;
            float v0 = acc[nt][half*2], v1 = acc[nt][half*2+1];
            int idx = row*256 + col;
            if (mode == 1) {
                __nv_bfloat162 ph = *(__nv_bfloat162*)(g_Phi + idx);
                __nv_bfloat162 pl = *(__nv_bfloat162*)(g_Plo + idx);
                float p0 = __bfloat162float(ph.x) + __bfloat162float(pl.x);
                float p1 = __bfloat162float(ph.y) + __bfloat162float(pl.y);
                v0 = 1.5f*p0 - 0.5f*v0;
                v1 = 1.5f*p1 - 0.5f*v1;
            } else if (mode == 2) {
                v0 *= snorm; v1 *= snorm;
                *(float2*)(g_M + idx) = make_float2(v0, v1);
            }
            __nv_bfloat16 h0, l0, h1, l1;
            bfsplit(v0, h0, l0); bfsplit(v1, h1, l1);
            *(__nv_bfloat162*)(Chi + idx) = __nv_bfloat162(h0, h1);
            *(__nv_bfloat162*)(Clo + idx) = __nv_bfloat162(l0, l1);
        }
    }
}

#define SOLVER_SMEM (2*((2*64*72 + 2*64*40)*2))   // 57344 B

// ---------------- persistent solver ----------------
__global__ void __launch_bounds__(256) k_solver(const float* __restrict__ rot) {
    extern __shared__ __align__(16) char dynsm[];
    __nv_bfloat16* ns = (__nv_bfloat16*)dynsm;
    int cta = blockIdx.x, tid = threadIdx.x, lane = tid & 31, wid = tid >> 5;
    __shared__ float red[256];
    __shared__ float s_scal[2];
    GBar gb;

    // phase 0: mean reduce
    {
        int wg = cta*8 + wid;
        if (wg < 256) {
            float s = g_msum[wg*NBATCH + lane] + g_msum[wg*NBATCH + 32 + lane];
            #pragma unroll
            for (int o = 16; o > 0; o >>= 1) s += __shfl_xor_sync(~0u, s, o);
            if (lane == 0) g_mean[wg] = s * (1.f / (float)MTOT);
        }
    }
    gbar(gb);

    // phase 1: sigfin
    {
        int idx4 = cta*256 + tid;
        int a = idx4 >> 6, b = (idx4 & 63) * 4;
        float4 s4 = make_float4(0.f, 0.f, 0.f, 0.f);
        if (a < 128 || b >= 128) {
            int q = (a < 128) ? ((b < 128) ? 0 : 1) : 2;
            const float* pp = g_part + (size_t)q*64*16384 + (a & 127)*128 + (b & 127);
            #pragma unroll 4
            for (int t = 0; t < 64; t++) {
                float4 v = __ldcg((const float4*)(pp + (size_t)t*16384));
                s4.x += v.x; s4.y += v.y; s4.z += v.z; s4.w += v.w;
            }
        } else {
            const float* pp = g_part + (size_t)1*64*16384 + b*128 + (a - 128);
            #pragma unroll 4
            for (int t = 0; t < 64; t++) {
                const float* bb = pp + (size_t)t*16384;
                s4.x += __ldcg(bb); s4.y += __ldcg(bb+128); s4.z += __ldcg(bb+256); s4.w += __ldcg(bb+384);
            }
        }
        float ma = g_mean[a];
        float4 mb = *(const float4*)(g_mean + b);
        float4 v = make_float4(s4.x*(1.f/(float)MTOT) - ma*mb.x,
                               s4.y*(1.f/(float)MTOT) - ma*mb.y,
                               s4.z*(1.f/(float)MTOT) - ma*mb.z,
                               s4.w*(1.f/(float)MTOT) - ma*mb.w);
        if (a == b)   v.x += EPSV;
        if (a == b+1) v.y += EPSV;
        if (a == b+2) v.z += EPSV;
        if (a == b+3) v.w += EPSV;
        *(float4*)(g_Sig + a*256 + b) = v;
    }
    gbar(gb);

    // phase 2: trace + init SigN hi/lo, P = I hi/lo, rot hi/lo
    {
        red[tid] = __ldcg(g_Sig + tid*257);
        __syncthreads();
        for (int o = 128; o > 0; o >>= 1) { if (tid < o) red[tid] += red[tid+o]; __syncthreads(); }
        if (tid == 0) { float tr = red[0]; s_scal[0] = 1.f/tr; s_scal[1] = sqrtf(1.f/tr); }
        __syncthreads();
        float sc = s_scal[0];
        int base = cta*1024 + tid*4;
        float4 sg = __ldcg((const float4*)(g_Sig + base));
        float4 rr = __ldcg((const float4*)(rot + base));
        int r = base >> 8, c = base & 255;
        float sv[4] = {sg.x*sc, sg.y*sc, sg.z*sc, sg.w*sc};
        float rv[4] = {rr.x, rr.y, rr.z, rr.w};
        __nv_bfloat16 sh[4], sl[4], rh[4], rl[4], ph[4], pl[4];
        #pragma unroll
        for (int k = 0; k < 4; k++) {
            bfsplit(sv[k], sh[k], sl[k]);
            bfsplit(rv[k], rh[k], rl[k]);
            ph[k] = __float2bfloat16((r == c + k) ? 1.f : 0.f);
            pl[k] = __float2bfloat16(0.f);
        }
        *(__nv_bfloat162*)(g_SNhi + base)     = __nv_bfloat162(sh[0], sh[1]);
        *(__nv_bfloat162*)(g_SNhi + base + 2) = __nv_bfloat162(sh[2], sh[3]);
        *(__nv_bfloat162*)(g_SNlo + base)     = __nv_bfloat162(sl[0], sl[1]);
        *(__nv_bfloat162*)(g_SNlo + base + 2) = __nv_bfloat162(sl[2], sl[3]);
        *(__nv_bfloat162*)(g_Rhi + base)      = __nv_bfloat162(rh[0], rh[1]);
        *(__nv_bfloat162*)(g_Rhi + base + 2)  = __nv_bfloat162(rh[2], rh[3]);
        *(__nv_bfloat162*)(g_Rlo + base)      = __nv_bfloat162(rl[0], rl[1]);
        *(__nv_bfloat162*)(g_Rlo + base + 2)  = __nv_bfloat162(rl[2], rl[3]);
        *(__nv_bfloat162*)(g_Phi + base)      = __nv_bfloat162(ph[0], ph[1]);
        *(__nv_bfloat162*)(g_Phi + base + 2)  = __nv_bfloat162(ph[2], ph[3]);
        *(__nv_bfloat162*)(g_Plo + base)      = __nv_bfloat162(pl[0], pl[1]);
        *(__nv_bfloat162*)(g_Plo + base + 2)  = __nv_bfloat162(pl[2], pl[3]);
    }
    gbar(gb);

    // phase 3: Newton-Schulz on tensor cores — all 64 CTAs busy each phase
    for (int it = 0; it < T_ITERS; it++) {
        if (cta < 32) {
            int t = cta;
            nt_mm2<64>(g_Phi, g_Plo, g_Phi, g_Plo, g_T1hi, g_T1lo,
                       (t >> 3)*64, (t & 7)*32, 0, 0.f, ns);
        } else {
            int t = cta - 32;
            nt_mm2<64>(g_Phi, g_Plo, g_SNhi, g_SNlo, g_T2hi, g_T2lo,
                       (t >> 3)*64, (t & 7)*32, 0, 0.f, ns);
        }
        gbar(gb);
        nt_mm2<32>(g_T1hi, g_T1lo, g_T2hi, g_T2lo, g_Phi, g_Plo,
                   (cta >> 3)*32, (cta & 7)*32, 1, 0.f, ns);
        gbar(gb);
    }

    // phase 4: M = s * rot * P  (all 64 CTAs, 32x32 tiles)
    nt_mm2<32>(g_Rhi, g_Rlo, g_Phi, g_Plo, g_Mhi, g_Mlo,
               (cta >> 3)*32, (cta & 7)*32, 2, s_scal[1], ns);
    gbar(gb);

    // phase 5: bias
    {
        int wg = cta*8 + wid;
        if (wg < 256) {
            float s = 0.f;
            #pragma unroll
            for (int k = 0; k < 8; k++)
                s += __ldcg(g_M + wg*256 + lane + k*32) * g_mean[lane + k*32];
            #pragma unroll
            for (int o = 16; o > 0; o >>= 1) s += __shfl_xor_sync(~0u, s, o);
            if (lane == 0) g_bias[wg] = s;
        }
    }
}

// ---------------- output GEMM, cp.async pipelined ----------------
#define OAT 18432u
#define OBT 17408u
#define OBOFF (2u*OAT)
#define OSTAGE (2u*OAT + 2u*OBT)
#define OUT_SMEM (2*OSTAGE)
__global__ void __launch_bounds__(256, 1) k_out_mma(float* __restrict__ out) {
    extern __shared__ char sm[];
    int p0 = blockIdx.x*128, d0 = blockIdx.y*128, n = blockIdx.z;
    int tid = threadIdx.x, lane = tid & 31, wid = tid >> 5;
    int wm = wid >> 2, wn = wid & 3;
    uint32_t sbase = smem_u32(sm);

    int rowA = tid >> 1, hA = tid & 1;
    int rowB = tid >> 2, qB = tid & 3;
    const __nv_bfloat16* gMh = g_Mhi + (d0 + rowA)*256 + hA*32;
    const __nv_bfloat16* gMl = g_Mlo + (d0 + rowA)*256 + hA*32;
    const __nv_bfloat16* gXh = g_xhi + ((size_t)n*CH + rowB)*HW + p0 + qB*32;
    const __nv_bfloat16* gXl = g_xlo + ((size_t)n*CH + rowB)*HW + p0 + qB*32;

    float acc[4][4][4];
    #pragma unroll
    for (int a = 0; a < 4; a++)
        #pragma unroll
        for (int b = 0; b < 4; b++)
            #pragma unroll
            for (int k = 0; k < 4; k++) acc[a][b][k] = 0.f;

    auto prefetch = [&](int cbi, int st) {
        uint32_t sb = sbase + st*OSTAGE;
        int cb = cbi*64;
        uint32_t dA = sb + rowA*144 + hA*64;
        #pragma unroll
        for (int j = 0; j < 4; j++) {
            cp16(dA + j*16,       gMh + cb + j*8);
            cp16(dA + OAT + j*16, gMl + cb + j*8);
        }
        uint32_t dB = sb + OBOFF + rowB*272 + qB*64;
        size_t go = (size_t)cb*HW;
        #pragma unroll
        for (int j = 0; j < 4; j++) {
            cp16(dB + j*16,       gXh + go + j*8);
            cp16(dB + OBT + j*16, gXl + go + j*8);
        }
    };

    prefetch(0, 0); cp_commit();
    for (int cbi = 0; cbi < 4; cbi++) {
        int cur = cbi & 1;
        if (cbi < 3) { prefetch(cbi+1, cur^1); cp_commit(); cp_wait<1>(); }
        else         { cp_wait<0>(); }
        __syncthreads();
        uint32_t sb = sbase + cur*OSTAGE;
        #pragma unroll
        for (int ks = 0; ks < 4; ks++) {
            int k0 = ks*16;
            uint32_t ah[4][4], al[4][4], bh[4][2], bl[4][2];
            int ar = lane & 15, ac = (lane >> 4) * 8;
            #pragma unroll
            for (int mt = 0; mt < 4; mt++) {
                uint32_t ao = sb + (wm*64 + mt*16 + ar)*144 + (k0 + ac)*2;
                ldm_x4(ah[mt], ao);
                ldm_x4(al[mt], ao + OAT);
            }
            int br = lane & 15;
            #pragma unroll
            for (int nt = 0; nt < 4; nt++) {
                uint32_t bo = sb + OBOFF + (k0 + br)*272 + (wn*32 + nt*8)*2;
                ldm_x2t(bh[nt], bo);
                ldm_x2t(bl[nt], bo + OBT);
            }
            #pragma unroll
            for (int mt = 0; mt < 4; mt++)
                #pragma unroll
                for (int nt = 0; nt < 4; nt++) {
                    mma_bf16(acc[mt][nt], ah[mt], bh[nt]);
                    mma_bf16(acc[mt][nt], ah[mt], bl[nt]);
                    mma_bf16(acc[mt][nt], al[mt], bh[nt]);
                }
        }
        __syncthreads();
    }
    float* On = out + (size_t)n * (CH*HW);
    int rg = lane >> 2, cg = (lane & 3)*2;
    #pragma unroll
    for (int mt = 0; mt < 4; mt++) {
        int d = d0 + wm*64 + mt*16 + rg;
        float b0 = g_bias[d], b1 = g_bias[d+8];
        #pragma unroll
        for (int nt = 0; nt < 4; nt++) {
            int p = p0 + wn*32 + nt*8 + cg;
            *(float2*)(On + (size_t)d*HW + p)     = make_float2(acc[mt][nt][0]-b0, acc[mt][nt][1]-b0);
            *(float2*)(On + (size_t)(d+8)*HW + p) = make_float2(acc[mt][nt][2]-b1, acc[mt][nt][3]-b1);
        }
    }
}

// ---------------- launch ----------------
extern "C" void kernel_launch(void* const* d_in, const int* in_sizes, int n_in,
                              void* d_out, int out_size) {
    const float* X   = (const float*)d_in[0];
    const float* rot = (const float*)d_in[1];
    if (n_in >= 2 && in_sizes[0] == CH*CH && in_sizes[1] != CH*CH) {
        X = (const float*)d_in[1]; rot = (const float*)d_in[0];
    }
    float* out = (float*)d_out;
    (void)out_size;

    cudaFuncSetAttribute(k_gram_mma, cudaFuncAttributeMaxDynamicSharedMemorySize, GRAM_SMEM);
    cudaFuncSetAttribute(k_out_mma,  cudaFuncAttributeMaxDynamicSharedMemorySize, OUT_SMEM);
    cudaFuncSetAttribute(k_solver,   cudaFuncAttributeMaxDynamicSharedMemorySize, SOLVER_SMEM);

    k_reset<<<1, 1>>>();
    k_conv1<<<dim3(256, 64), 256>>>(X);
    k_gram_mma<<<dim3(3, 64), 256, GRAM_SMEM>>>();
    k_solver<<<NCTA, 256, SOLVER_SMEM>>>(rot);
    k_out_mma<<<dim3(8, 2, 64), 256, OUT_SMEM>>>(out);
}

// round 9
// speedup vs baseline: 1.4191x; 1.0557x over previous
#include <cuda_runtime.h>
#include <cuda_bf16.h>
#include <math.h>
#include <stdint.h>

#define CH 256
#define NBATCH 64
#define HW 1024
#define MTOT 65536
#define EPSV 1e-5f
#define T_ITERS 10
#define NCTA 64

// ---------------- device scratch (16B-aligned: float4/cp.async access) ----------------
__device__ float g_mean[CH];
__device__ float g_msum[CH*NBATCH];
__device__ float g_bias[CH];
__device__ float g_Sig [CH*CH];
__device__ float g_M   [CH*CH];
__device__ float g_part[192*16384];
__device__ __align__(16) __nv_bfloat16 g_xhi[64L*256*1024];
__device__ __align__(16) __nv_bfloat16 g_xlo[64L*256*1024];
__device__ __align__(16) __nv_bfloat16 g_Mhi [CH*CH], g_Mlo [CH*CH];
__device__ __align__(16) __nv_bfloat16 g_Phi [CH*CH], g_Plo [CH*CH];
__device__ __align__(16) __nv_bfloat16 g_T1hi[CH*CH], g_T1lo[CH*CH];
__device__ __align__(16) __nv_bfloat16 g_T2hi[CH*CH], g_T2lo[CH*CH];
__device__ __align__(16) __nv_bfloat16 g_SNhi[CH*CH], g_SNlo[CH*CH];
__device__ __align__(16) __nv_bfloat16 g_Rhi [CH*CH], g_Rlo [CH*CH];
__device__ unsigned g_bar_cnt;

// ---------------- helpers ----------------
__device__ __forceinline__ uint32_t smem_u32(const void* p) {
    uint32_t a;
    asm("{ .reg .u64 t; cvta.to.shared.u64 t, %1; cvt.u32.u64 %0, t; }" : "=r"(a) : "l"(p));
    return a;
}
__device__ __forceinline__ void ldm_x4(uint32_t* r, uint32_t addr) {
    asm volatile("ldmatrix.sync.aligned.m8n8.x4.shared.b16 {%0,%1,%2,%3}, [%4];"
        : "=r"(r[0]), "=r"(r[1]), "=r"(r[2]), "=r"(r[3]) : "r"(addr));
}
__device__ __forceinline__ void ldm_x2(uint32_t* r, uint32_t addr) {
    asm volatile("ldmatrix.sync.aligned.m8n8.x2.shared.b16 {%0,%1}, [%2];"
        : "=r"(r[0]), "=r"(r[1]) : "r"(addr));
}
__device__ __forceinline__ void ldm_x2t(uint32_t* r, uint32_t addr) {
    asm volatile("ldmatrix.sync.aligned.m8n8.x2.trans.shared.b16 {%0,%1}, [%2];"
        : "=r"(r[0]), "=r"(r[1]) : "r"(addr));
}
__device__ __forceinline__ void mma_bf16(float* c, const uint32_t* a, const uint32_t* b) {
    asm volatile("mma.sync.aligned.m16n8k16.row.col.f32.bf16.bf16.f32 "
        "{%0,%1,%2,%3}, {%4,%5,%6,%7}, {%8,%9}, {%0,%1,%2,%3};"
        : "+f"(c[0]), "+f"(c[1]), "+f"(c[2]), "+f"(c[3])
        : "r"(a[0]), "r"(a[1]), "r"(a[2]), "r"(a[3]), "r"(b[0]), "r"(b[1]));
}
__device__ __forceinline__ void cp16(uint32_t dst, const void* src) {
    asm volatile("cp.async.cg.shared.global [%0], [%1], 16;" :: "r"(dst), "l"(src));
}
__device__ __forceinline__ void cp_commit() { asm volatile("cp.async.commit_group;" ::: "memory"); }
template<int N> __device__ __forceinline__ void cp_wait() {
    asm volatile("cp.async.wait_group %0;" :: "n"(N) : "memory");
}
__device__ __forceinline__ void bfsplit(float v, __nv_bfloat16& h, __nv_bfloat16& l) {
    h = __float2bfloat16(v);
    l = __float2bfloat16(v - __bfloat162float(h));
}

// ---------------- monotonic grid barrier: release/acquire (grid.sync pattern) ----------------
struct GBar { unsigned nbar = 0; };
__device__ __forceinline__ void gbar(GBar& gb) {
    __syncthreads();
    gb.nbar++;
    if (threadIdx.x == 0) {
        unsigned target = gb.nbar * NCTA;
        asm volatile("red.release.gpu.add.u32 [%0], 1;" :: "l"(&g_bar_cnt) : "memory");
        unsigned v;
        do {
            asm volatile("ld.acquire.gpu.u32 %0, [%1];" : "=r"(v) : "l"(&g_bar_cnt) : "memory");
        } while (v < target);
    }
    __syncthreads();
}

// ---------------- convert X -> bf16 hi/lo + per-(c,n) sums (+ barrier counter reset) ----------------
__global__ void __launch_bounds__(256) k_conv1(const float* __restrict__ X) {
    int c = blockIdx.x, n = blockIdx.y, t = threadIdx.x;
    if (c == 0 && n == 0 && t == 0) g_bar_cnt = 0;
    size_t base = ((size_t)n*CH + c) * HW;
    float4 v = *(const float4*)(X + base + t*4);
    float f[4] = {v.x, v.y, v.z, v.w};
    __nv_bfloat16 h[4], l[4];
    #pragma unroll
    for (int k = 0; k < 4; k++) bfsplit(f[k], h[k], l[k]);
    __nv_bfloat162* ph = (__nv_bfloat162*)(g_xhi + base);
    __nv_bfloat162* pl = (__nv_bfloat162*)(g_xlo + base);
    ph[t*2]   = __nv_bfloat162(h[0], h[1]);
    ph[t*2+1] = __nv_bfloat162(h[2], h[3]);
    pl[t*2]   = __nv_bfloat162(l[0], l[1]);
    pl[t*2+1] = __nv_bfloat162(l[2], l[3]);
    float s = f[0] + f[1] + f[2] + f[3];
    __shared__ float sm[256];
    sm[t] = s; __syncthreads();
    for (int o = 128; o > 0; o >>= 1) { if (t < o) sm[t] += sm[t+o]; __syncthreads(); }
    if (t == 0) g_msum[c*NBATCH + n] = sm[0];
}

// ---------------- Gram: quadrants (0,0),(0,1),(1,1) x 64 n-splits, 3-stage cp.async ----------------
#define GT 18432u
#define GSTAGE (4u*GT)
#define GRAM_SMEM (3*GSTAGE)
__global__ void __launch_bounds__(256, 1) k_gram_mma() {
    extern __shared__ char sm[];
    int q = blockIdx.x, n = blockIdx.y;
    int ci0 = (q == 2) ? 128 : 0;
    int cj0 = (q == 0) ? 0 : 128;
    bool diag = (q != 1);
    int tid = threadIdx.x, lane = tid & 31, wid = tid >> 5;
    int wm = wid >> 2, wn = wid & 3;
    uint32_t sbase = smem_u32(sm);

    int rowL = tid >> 1, hL = tid & 1;
    const __nv_bfloat16* gAh = g_xhi + ((size_t)n*CH + ci0 + rowL)*HW + hL*32;
    const __nv_bfloat16* gAl = g_xlo + ((size_t)n*CH + ci0 + rowL)*HW + hL*32;
    const __nv_bfloat16* gBh = g_xhi + ((size_t)n*CH + cj0 + rowL)*HW + hL*32;
    const __nv_bfloat16* gBl = g_xlo + ((size_t)n*CH + cj0 + rowL)*HW + hL*32;

    float acc[4][4][4];
    #pragma unroll
    for (int a = 0; a < 4; a++)
        #pragma unroll
        for (int b = 0; b < 4; b++)
            #pragma unroll
            for (int k = 0; k < 4; k++) acc[a][b][k] = 0.f;

    auto prefetch = [&](int kb, int st) {
        uint32_t sb = sbase + st*GSTAGE;
        int pb = kb*64;
        uint32_t dA = sb + rowL*144 + hL*64;
        #pragma unroll
        for (int j = 0; j < 4; j++) {
            cp16(dA + j*16,      gAh + pb + j*8);
            cp16(dA + GT + j*16, gAl + pb + j*8);
        }
        if (!diag) {
            uint32_t dB = dA + 2*GT;
            #pragma unroll
            for (int j = 0; j < 4; j++) {
                cp16(dB + j*16,      gBh + pb + j*8);
                cp16(dB + GT + j*16, gBl + pb + j*8);
            }
        }
    };

    prefetch(0, 0); cp_commit();
    prefetch(1, 1); cp_commit();
    for (int kb = 0; kb < 16; kb++) {
        int cur = kb % 3;
        if (kb < 15) cp_wait<1>(); else cp_wait<0>();
        __syncthreads();
        if (kb + 2 < 16) { prefetch(kb+2, (kb+2) % 3); cp_commit(); }
        uint32_t sb = sbase + cur*GSTAGE;
        uint32_t bb = sb + (diag ? 0 : 2*GT);
        #pragma unroll
        for (int ks = 0; ks < 4; ks++) {
            int k0 = ks*16;
            uint32_t ah[4][4], al[4][4], bh[4][2], bl[4][2];
            int ar = lane & 15, ac = (lane >> 4) * 8;
            #pragma unroll
            for (int mt = 0; mt < 4; mt++) {
                uint32_t ao = sb + (wm*64 + mt*16 + ar)*144 + (k0 + ac)*2;
                ldm_x4(ah[mt], ao);
                ldm_x4(al[mt], ao + GT);
            }
            int br = lane & 7, bc = ((lane >> 3) & 1) * 8;
            #pragma unroll
            for (int nt = 0; nt < 4; nt++) {
                uint32_t bo = bb + (wn*32 + nt*8 + br)*144 + (k0 + bc)*2;
                ldm_x2(bh[nt], bo);
                ldm_x2(bl[nt], bo + GT);
            }
            #pragma unroll
            for (int mt = 0; mt < 4; mt++)
                #pragma unroll
                for (int nt = 0; nt < 4; nt++) {
                    mma_bf16(acc[mt][nt], ah[mt], bh[nt]);
                    mma_bf16(acc[mt][nt], ah[mt], bl[nt]);
                    mma_bf16(acc[mt][nt], al[mt], bh[nt]);
                }
        }
    }
    float* pout = g_part + ((size_t)q*64 + n)*16384;
    int rg = lane >> 2, cg = (lane & 3)*2;
    #pragma unroll
    for (int mt = 0; mt < 4; mt++)
        #pragma unroll
        for (int nt = 0; nt < 4; nt++) {
            int r0 = wm*64 + mt*16 + rg, c0 = wn*32 + nt*8 + cg;
            *(float2*)(pout + r0*128 + c0)     = make_float2(acc[mt][nt][0], acc[mt][nt][1]);
            *(float2*)(pout + (r0+8)*128 + c0) = make_float2(acc[mt][nt][2], acc[mt][nt][3]);
        }
}

// ---------------- pipelined tensor tile matmul for the solver (3-stage) ----------------
template<int TM>
__device__ __forceinline__ void nt_mm2(
    const __nv_bfloat16* __restrict__ Ah, const __nv_bfloat16* __restrict__ Al,
    const __nv_bfloat16* __restrict__ Bh, const __nv_bfloat16* __restrict__ Bl,
    __nv_bfloat16* __restrict__ Chi, __nv_bfloat16* __restrict__ Clo,
    int tr, int tc, int mode, float snorm, __nv_bfloat16* ns)
{
    constexpr int SA  = TM*72;
    constexpr int SB  = 64*40;
    constexpr int STB = (2*SA + 2*SB)*2;   // stage bytes
    constexpr int NT  = (TM == 64) ? 2 : 1;
    constexpr int WNW = (TM == 64) ? 16 : 8;
    int tid = threadIdx.x, lane = tid & 31, wid = tid >> 5;
    int wm = (TM == 64) ? (wid >> 1) : (wid >> 2);
    int wn = (TM == 64) ? (wid & 1)  : (wid & 3);
    uint32_t base = smem_u32(ns);

    float acc[NT][4];
    #pragma unroll
    for (int nt = 0; nt < NT; nt++)
        #pragma unroll
        for (int k = 0; k < 4; k++) acc[nt][k] = 0.f;

    int brow = tid >> 2, bcol = tid & 3;

    auto stage = [&](int kb, int st) {
        uint32_t sb = base + st*STB;
        #pragma unroll
        for (int c = 0; c < TM*8; c += 256) {
            int cc = c + tid;
            int row = cc >> 3, col = cc & 7;
            uint32_t d = sb + row*144 + col*16;
            cp16(d,        Ah + (tr + row)*256 + kb + col*8);
            cp16(d + SA*2, Al + (tr + row)*256 + kb + col*8);
        }
        uint32_t dB = sb + 2*(SA*2) + brow*80 + bcol*16;
        cp16(dB,        Bh + (kb + brow)*256 + tc + bcol*8);
        cp16(dB + SB*2, Bl + (kb + brow)*256 + tc + bcol*8);
    };

    stage(0, 0); cp_commit();
    stage(64, 1); cp_commit();
    for (int kb = 0; kb < 4; kb++) {
        int cur = kb % 3;
        if (kb < 3) cp_wait<1>(); else cp_wait<0>();
        __syncthreads();
        if (kb + 2 < 4) { stage((kb+2)*64, (kb+2) % 3); cp_commit(); }
        uint32_t sb  = base + cur*STB;
        uint32_t sbB = sb + 2*(SA*2);
        #pragma unroll
        for (int ks = 0; ks < 4; ks++) {
            int k0 = ks*16;
            uint32_t ah[4], al[4], bh[NT][2], bl[NT][2];
            uint32_t ao = sb + (wm*16 + (lane & 15))*144 + (k0 + (lane >> 4)*8)*2;
            ldm_x4(ah, ao);
            ldm_x4(al, ao + SA*2);
            #pragma unroll
            for (int nt = 0; nt < NT; nt++) {
                uint32_t bo = sbB + (k0 + (lane & 15))*80 + (wn*WNW + nt*8)*2;
                ldm_x2t(bh[nt], bo);
                ldm_x2t(bl[nt], bo + SB*2);
            }
            #pragma unroll
            for (int nt = 0; nt < NT; nt++) {
                mma_bf16(acc[nt], ah, bh[nt]);
                mma_bf16(acc[nt], ah, bl[nt]);
                mma_bf16(acc[nt], al, bh[nt]);
            }
        }
    }
    int rg = lane >> 2, cg = (lane & 3)*2;
    #pragma unroll
    for (int nt = 0; nt < NT; nt++) {
        int col = tc + wn*WNW + nt*8 + cg;
        #pragma unroll
        for (int half = 0; half < 2; half++) {
            int row = tr + wm*16 + rg + half*8;
            float v0 = acc[nt][half*2], v1 = acc[nt][half*2+1];
            int idx = row*256 + col;
            if (mode == 1) {
                __nv_bfloat162 ph = *(__nv_bfloat162*)(g_Phi + idx);
                __nv_bfloat162 pl = *(__nv_bfloat162*)(g_Plo + idx);
                float p0 = __bfloat162float(ph.x) + __bfloat162float(pl.x);
                float p1 = __bfloat162float(ph.y) + __bfloat162float(pl.y);
                v0 = 1.5f*p0 - 0.5f*v0;
                v1 = 1.5f*p1 - 0.5f*v1;
            } else if (mode == 2) {
                v0 *= snorm; v1 *= snorm;
                *(float2*)(g_M + idx) = make_float2(v0, v1);
            }
            __nv_bfloat16 h0, l0, h1, l1;
            bfsplit(v0, h0, l0); bfsplit(v1, h1, l1);
            *(__nv_bfloat162*)(Chi + idx) = __nv_bfloat162(h0, h1);
            *(__nv_bfloat162*)(Clo + idx) = __nv_bfloat162(l0, l1);
        }
    }
}

#define SOLVER_SMEM (3*((2*64*72 + 2*64*40)*2))   // 86016 B

// ---------------- persistent solver ----------------
__global__ void __launch_bounds__(256) k_solver(const float* __restrict__ rot) {
    extern __shared__ __align__(16) char dynsm[];
    __nv_bfloat16* ns = (__nv_bfloat16*)dynsm;
    int cta = blockIdx.x, tid = threadIdx.x, lane = tid & 31, wid = tid >> 5;
    __shared__ float red[256];
    __shared__ float s_scal[2];
    GBar gb;

    // phase 0: mean reduce
    {
        int wg = cta*8 + wid;
        if (wg < 256) {
            float s = g_msum[wg*NBATCH + lane] + g_msum[wg*NBATCH + 32 + lane];
            #pragma unroll
            for (int o = 16; o > 0; o >>= 1) s += __shfl_xor_sync(~0u, s, o);
            if (lane == 0) g_mean[wg] = s * (1.f / (float)MTOT);
        }
    }
    gbar(gb);

    // phase 1: sigfin
    {
        int idx4 = cta*256 + tid;
        int a = idx4 >> 6, b = (idx4 & 63) * 4;
        float4 s4 = make_float4(0.f, 0.f, 0.f, 0.f);
        if (a < 128 || b >= 128) {
            int q = (a < 128) ? ((b < 128) ? 0 : 1) : 2;
            const float* pp = g_part + (size_t)q*64*16384 + (a & 127)*128 + (b & 127);
            #pragma unroll 4
            for (int t = 0; t < 64; t++) {
                float4 v = __ldcg((const float4*)(pp + (size_t)t*16384));
                s4.x += v.x; s4.y += v.y; s4.z += v.z; s4.w += v.w;
            }
        } else {
            const float* pp = g_part + (size_t)1*64*16384 + b*128 + (a - 128);
            #pragma unroll 4
            for (int t = 0; t < 64; t++) {
                const float* bb = pp + (size_t)t*16384;
                s4.x += __ldcg(bb); s4.y += __ldcg(bb+128); s4.z += __ldcg(bb+256); s4.w += __ldcg(bb+384);
            }
        }
        float ma = g_mean[a];
        float4 mb = *(const float4*)(g_mean + b);
        float4 v = make_float4(s4.x*(1.f/(float)MTOT) - ma*mb.x,
                               s4.y*(1.f/(float)MTOT) - ma*mb.y,
                               s4.z*(1.f/(float)MTOT) - ma*mb.z,
                               s4.w*(1.f/(float)MTOT) - ma*mb.w);
        if (a == b)   v.x += EPSV;
        if (a == b+1) v.y += EPSV;
        if (a == b+2) v.z += EPSV;
        if (a == b+3) v.w += EPSV;
        *(float4*)(g_Sig + a*256 + b) = v;
    }
    gbar(gb);

    // phase 2: trace + init SigN hi/lo, P = I hi/lo, rot hi/lo
    {
        red[tid] = __ldcg(g_Sig + tid*257);
        __syncthreads();
        for (int o = 128; o > 0; o >>= 1) { if (tid < o) red[tid] += red[tid+o]; __syncthreads(); }
        if (tid == 0) { float tr = red[0]; s_scal[0] = 1.f/tr; s_scal[1] = sqrtf(1.f/tr); }
        __syncthreads();
        float sc = s_scal[0];
        int base = cta*1024 + tid*4;
        float4 sg = __ldcg((const float4*)(g_Sig + base));
        float4 rr = __ldcg((const float4*)(rot + base));
        int r = base >> 8, c = base & 255;
        float sv[4] = {sg.x*sc, sg.y*sc, sg.z*sc, sg.w*sc};
        float rv[4] = {rr.x, rr.y, rr.z, rr.w};
        __nv_bfloat16 sh[4], sl[4], rh[4], rl[4], ph[4], pl[4];
        #pragma unroll
        for (int k = 0; k < 4; k++) {
            bfsplit(sv[k], sh[k], sl[k]);
            bfsplit(rv[k], rh[k], rl[k]);
            ph[k] = __float2bfloat16((r == c + k) ? 1.f : 0.f);
            pl[k] = __float2bfloat16(0.f);
        }
        *(__nv_bfloat162*)(g_SNhi + base)     = __nv_bfloat162(sh[0], sh[1]);
        *(__nv_bfloat162*)(g_SNhi + base + 2) = __nv_bfloat162(sh[2], sh[3]);
        *(__nv_bfloat162*)(g_SNlo + base)     = __nv_bfloat162(sl[0], sl[1]);
        *(__nv_bfloat162*)(g_SNlo + base + 2) = __nv_bfloat162(sl[2], sl[3]);
        *(__nv_bfloat162*)(g_Rhi + base)      = __nv_bfloat162(rh[0], rh[1]);
        *(__nv_bfloat162*)(g_Rhi + base + 2)  = __nv_bfloat162(rh[2], rh[3]);
        *(__nv_bfloat162*)(g_Rlo + base)      = __nv_bfloat162(rl[0], rl[1]);
        *(__nv_bfloat162*)(g_Rlo + base + 2)  = __nv_bfloat162(rl[2], rl[3]);
        *(__nv_bfloat162*)(g_Phi + base)      = __nv_bfloat162(ph[0], ph[1]);
        *(__nv_bfloat162*)(g_Phi + base + 2)  = __nv_bfloat162(ph[2], ph[3]);
        *(__nv_bfloat162*)(g_Plo + base)      = __nv_bfloat162(pl[0], pl[1]);
        *(__nv_bfloat162*)(g_Plo + base + 2)  = __nv_bfloat162(pl[2], pl[3]);
    }
    gbar(gb);

    // phase 3: Newton-Schulz on tensor cores — all 64 CTAs busy each phase
    for (int it = 0; it < T_ITERS; it++) {
        if (cta < 32) {
            int t = cta;
            nt_mm2<64>(g_Phi, g_Plo, g_Phi, g_Plo, g_T1hi, g_T1lo,
                       (t >> 3)*64, (t & 7)*32, 0, 0.f, ns);
        } else {
            int t = cta - 32;
            nt_mm2<64>(g_Phi, g_Plo, g_SNhi, g_SNlo, g_T2hi, g_T2lo,
                       (t >> 3)*64, (t & 7)*32, 0, 0.f, ns);
        }
        gbar(gb);
        nt_mm2<32>(g_T1hi, g_T1lo, g_T2hi, g_T2lo, g_Phi, g_Plo,
                   (cta >> 3)*32, (cta & 7)*32, 1, 0.f, ns);
        gbar(gb);
    }

    // phase 4: M = s * rot * P  (all 64 CTAs, 32x32 tiles)
    nt_mm2<32>(g_Rhi, g_Rlo, g_Phi, g_Plo, g_Mhi, g_Mlo,
               (cta >> 3)*32, (cta & 7)*32, 2, s_scal[1], ns);
    gbar(gb);

    // phase 5: bias
    {
        int wg = cta*8 + wid;
        if (wg < 256) {
            float s = 0.f;
            #pragma unroll
            for (int k = 0; k < 8; k++)
                s += __ldcg(g_M + wg*256 + lane + k*32) * g_mean[lane + k*32];
            #pragma unroll
            for (int o = 16; o > 0; o >>= 1) s += __shfl_xor_sync(~0u, s, o);
            if (lane == 0) g_bias[wg] = s;
        }
    }
}

// ---------------- output GEMM, 3-stage cp.async ----------------
#define OAT 18432u
#define OBT 17408u
#define OBOFF (2u*OAT)
#define OSTAGE (2u*OAT + 2u*OBT)
#define OUT_SMEM (3*OSTAGE)
__global__ void __launch_bounds__(256, 1) k_out_mma(float* __restrict__ out) {
    extern __shared__ char sm[];
    int p0 = blockIdx.x*128, d0 = blockIdx.y*128, n = blockIdx.z;
    int tid = threadIdx.x, lane = tid & 31, wid = tid >> 5;
    int wm = wid >> 2, wn = wid & 3;
    uint32_t sbase = smem_u32(sm);

    int rowA = tid >> 1, hA = tid & 1;
    int rowB = tid >> 2, qB = tid & 3;
    const __nv_bfloat16* gMh = g_Mhi + (d0 + rowA)*256 + hA*32;
    const __nv_bfloat16* gMl = g_Mlo + (d0 + rowA)*256 + hA*32;
    const __nv_bfloat16* gXh = g_xhi + ((size_t)n*CH + rowB)*HW + p0 + qB*32;
    const __nv_bfloat16* gXl = g_xlo + ((size_t)n*CH + rowB)*HW + p0 + qB*32;

    float acc[4][4][4];
    #pragma unroll
    for (int a = 0; a < 4; a++)
        #pragma unroll
        for (int b = 0; b < 4; b++)
            #pragma unroll
            for (int k = 0; k < 4; k++) acc[a][b][k] = 0.f;

    auto prefetch = [&](int cbi, int st) {
        uint32_t sb = sbase + st*OSTAGE;
        int cb = cbi*64;
        uint32_t dA = sb + rowA*144 + hA*64;
        #pragma unroll
        for (int j = 0; j < 4; j++) {
            cp16(dA + j*16,       gMh + cb + j*8);
            cp16(dA + OAT + j*16, gMl + cb + j*8);
        }
        uint32_t dB = sb + OBOFF + rowB*272 + qB*64;
        size_t go = (size_t)cb*HW;
        #pragma unroll
        for (int j = 0; j < 4; j++) {
            cp16(dB + j*16,       gXh + go + j*8);
            cp16(dB + OBT + j*16, gXl + go + j*8);
        }
    };

    prefetch(0, 0); cp_commit();
    prefetch(1, 1); cp_commit();
    for (int cbi = 0; cbi < 4; cbi++) {
        int cur = cbi % 3;
        if (cbi < 3) cp_wait<1>(); else cp_wait<0>();
        __syncthreads();
        if (cbi + 2 < 4) { prefetch(cbi+2, (cbi+2) % 3); cp_commit(); }
        uint32_t sb = sbase + cur*OSTAGE;
        #pragma unroll
        for (int ks = 0; ks < 4; ks++) {
            int k0 = ks*16;
            uint32_t ah[4][4], al[4][4], bh[4][2], bl[4][2];
            int ar = lane & 15, ac = (lane >> 4) * 8;
            #pragma unroll
            for (int mt = 0; mt < 4; mt++) {
                uint32_t ao = sb + (wm*64 + mt*16 + ar)*144 + (k0 + ac)*2;
                ldm_x4(ah[mt], ao);
                ldm_x4(al[mt], ao + OAT);
            }
            int br = lane & 15;
            #pragma unroll
            for (int nt = 0; nt < 4; nt++) {
                uint32_t bo = sb + OBOFF + (k0 + br)*272 + (wn*32 + nt*8)*2;
                ldm_x2t(bh[nt], bo);
                ldm_x2t(bl[nt], bo + OBT);
            }
            #pragma unroll
            for (int mt = 0; mt < 4; mt++)
                #pragma unroll
                for (int nt = 0; nt < 4; nt++) {
                    mma_bf16(acc[mt][nt], ah[mt], bh[nt]);
                    mma_bf16(acc[mt][nt], ah[mt], bl[nt]);
                    mma_bf16(acc[mt][nt], al[mt], bh[nt]);
                }
        }
    }
    float* On = out + (size_t)n * (CH*HW);
    int rg = lane >> 2, cg = (lane & 3)*2;
    #pragma unroll
    for (int mt = 0; mt < 4; mt++) {
        int d = d0 + wm*64 + mt*16 + rg;
        float b0 = g_bias[d], b1 = g_bias[d+8];
        #pragma unroll
        for (int nt = 0; nt < 4; nt++) {
            int p = p0 + wn*32 + nt*8 + cg;
            *(float2*)(On + (size_t)d*HW + p)     = make_float2(acc[mt][nt][0]-b0, acc[mt][nt][1]-b0);
            *(float2*)(On + (size_t)(d+8)*HW + p) = make_float2(acc[mt][nt][2]-b1, acc[mt][nt][3]-b1);
        }
    }
}

// ---------------- launch ----------------
extern "C" void kernel_launch(void* const* d_in, const int* in_sizes, int n_in,
                              void* d_out, int out_size) {
    const float* X   = (const float*)d_in[0];
    const float* rot = (const float*)d_in[1];
    if (n_in >= 2 && in_sizes[0] == CH*CH && in_sizes[1] != CH*CH) {
        X = (const float*)d_in[1]; rot = (const float*)d_in[0];
    }
    float* out = (float*)d_out;
    (void)out_size;

    cudaFuncSetAttribute(k_gram_mma, cudaFuncAttributeMaxDynamicSharedMemorySize, GRAM_SMEM);
    cudaFuncSetAttribute(k_out_mma,  cudaFuncAttributeMaxDynamicSharedMemorySize, OUT_SMEM);
    cudaFuncSetAttribute(k_solver,   cudaFuncAttributeMaxDynamicSharedMemorySize, SOLVER_SMEM);

    k_conv1<<<dim3(256, 64), 256>>>(X);
    k_gram_mma<<<dim3(3, 64), 256, GRAM_SMEM>>>();
    k_solver<<<NCTA, 256, SOLVER_SMEM>>>(rot);
    k_out_mma<<<dim3(8, 2, 64), 256, OUT_SMEM>>>(out);
}

// round 12
// speedup vs baseline: 1.5203x; 1.0713x over previous
#include <cuda_runtime.h>
#include <cuda_bf16.h>
#include <math.h>
#include <stdint.h>

#define CH 256
#define NBATCH 64
#define HW 1024
#define MTOT 65536
#define EPSV 1e-5f
#define T_ITERS 10
#define NCTA 64

// ---------------- device scratch (16B-aligned: float4/cp.async access) ----------------
__device__ float g_mean[CH];
__device__ float g_msum[CH*NBATCH];
__device__ float g_bias[CH];
__device__ float g_Sig [CH*CH];
__device__ float g_M   [CH*CH];
__device__ float g_part[192*16384];
__device__ __align__(16) __nv_bfloat16 g_xhi[64L*256*1024];
__device__ __align__(16) __nv_bfloat16 g_xlo[64L*256*1024];
__device__ __align__(16) __nv_bfloat16 g_Mhi [CH*CH], g_Mlo [CH*CH];
__device__ __align__(16) __nv_bfloat16 g_Phi [CH*CH], g_Plo [CH*CH];
__device__ __align__(16) __nv_bfloat16 g_T1hi[CH*CH], g_T1lo[CH*CH];
__device__ __align__(16) __nv_bfloat16 g_T2hi[CH*CH], g_T2lo[CH*CH];
__device__ __align__(16) __nv_bfloat16 g_SNhi[CH*CH], g_SNlo[CH*CH];
__device__ __align__(16) __nv_bfloat16 g_Rhi [CH*CH], g_Rlo [CH*CH];
__device__ unsigned g_bar_cnt;

// ---------------- helpers ----------------
__device__ __forceinline__ uint32_t smem_u32(const void* p) {
    uint32_t a;
    asm("{ .reg .u64 t; cvta.to.shared.u64 t, %1; cvt.u32.u64 %0, t; }" : "=r"(a) : "l"(p));
    return a;
}
__device__ __forceinline__ void ldm_x4(uint32_t* r, uint32_t addr) {
    asm volatile("ldmatrix.sync.aligned.m8n8.x4.shared.b16 {%0,%1,%2,%3}, [%4];"
        : "=r"(r[0]), "=r"(r[1]), "=r"(r[2]), "=r"(r[3]) : "r"(addr));
}
__device__ __forceinline__ void ldm_x2(uint32_t* r, uint32_t addr) {
    asm volatile("ldmatrix.sync.aligned.m8n8.x2.shared.b16 {%0,%1}, [%2];"
        : "=r"(r[0]), "=r"(r[1]) : "r"(addr));
}
__device__ __forceinline__ void ldm_x2t(uint32_t* r, uint32_t addr) {
    asm volatile("ldmatrix.sync.aligned.m8n8.x2.trans.shared.b16 {%0,%1}, [%2];"
        : "=r"(r[0]), "=r"(r[1]) : "r"(addr));
}
__device__ __forceinline__ void mma_bf16(float* c, const uint32_t* a, const uint32_t* b) {
    asm volatile("mma.sync.aligned.m16n8k16.row.col.f32.bf16.bf16.f32 "
        "{%0,%1,%2,%3}, {%4,%5,%6,%7}, {%8,%9}, {%0,%1,%2,%3};"
        : "+f"(c[0]), "+f"(c[1]), "+f"(c[2]), "+f"(c[3])
        : "r"(a[0]), "r"(a[1]), "r"(a[2]), "r"(a[3]), "r"(b[0]), "r"(b[1]));
}
__device__ __forceinline__ void cp16(uint32_t dst, const void* src) {
    asm volatile("cp.async.cg.shared.global [%0], [%1], 16;" :: "r"(dst), "l"(src));
}
__device__ __forceinline__ void cp_commit() { asm volatile("cp.async.commit_group;" ::: "memory"); }
template<int N> __device__ __forceinline__ void cp_wait() {
    asm volatile("cp.async.wait_group %0;" :: "n"(N) : "memory");
}
__device__ __forceinline__ void bfsplit(float v, __nv_bfloat16& h, __nv_bfloat16& l) {
    h = __float2bfloat16(v);
    l = __float2bfloat16(v - __bfloat162float(h));
}

// ---------------- monotonic grid barrier: release/acquire ----------------
struct GBar { unsigned nbar = 0; };
__device__ __forceinline__ void gbar(GBar& gb) {
    __syncthreads();
    gb.nbar++;
    if (threadIdx.x == 0) {
        unsigned target = gb.nbar * NCTA;
        asm volatile("red.release.gpu.add.u32 [%0], 1;" :: "l"(&g_bar_cnt) : "memory");
        unsigned v;
        do {
            asm volatile("ld.acquire.gpu.u32 %0, [%1];" : "=r"(v) : "l"(&g_bar_cnt) : "memory");
        } while (v < target);
    }
    __syncthreads();
}

// ---------------- convert X -> bf16 hi/lo + per-(c,n) sums (+ barrier counter reset) ----------------
__global__ void __launch_bounds__(256) k_conv1(const float* __restrict__ X) {
    int c = blockIdx.x, n = blockIdx.y, t = threadIdx.x;
    if (c == 0 && n == 0 && t == 0) g_bar_cnt = 0;
    size_t base = ((size_t)n*CH + c) * HW;
    float4 v = *(const float4*)(X + base + t*4);
    float f[4] = {v.x, v.y, v.z, v.w};
    __nv_bfloat16 h[4], l[4];
    #pragma unroll
    for (int k = 0; k < 4; k++) bfsplit(f[k], h[k], l[k]);
    __nv_bfloat162* ph = (__nv_bfloat162*)(g_xhi + base);
    __nv_bfloat162* pl = (__nv_bfloat162*)(g_xlo + base);
    ph[t*2]   = __nv_bfloat162(h[0], h[1]);
    ph[t*2+1] = __nv_bfloat162(h[2], h[3]);
    pl[t*2]   = __nv_bfloat162(l[0], l[1]);
    pl[t*2+1] = __nv_bfloat162(l[2], l[3]);
    float s = f[0] + f[1] + f[2] + f[3];
    __shared__ float sm[256];
    sm[t] = s; __syncthreads();
    for (int o = 128; o > 0; o >>= 1) { if (t < o) sm[t] += sm[t+o]; __syncthreads(); }
    if (t == 0) g_msum[c*NBATCH + n] = sm[0];
}

// ---------------- Gram: quadrants x 64 n-splits, 3-stage cp.async, 512 threads ----------------
#define GT 18432u
#define GSTAGE (4u*GT)
#define GRAM_SMEM (3*GSTAGE)
__global__ void __launch_bounds__(512, 1) k_gram_mma() {
    extern __shared__ char sm[];
    int q = blockIdx.x, n = blockIdx.y;
    int ci0 = (q == 2) ? 128 : 0;
    int cj0 = (q == 0) ? 0 : 128;
    bool diag = (q != 1);
    int tid = threadIdx.x, lane = tid & 31, wid = tid >> 5;
    int wm = wid >> 2, wn = wid & 3;        // 4 x 4 warps, 32x32 tiles
    uint32_t sbase = smem_u32(sm);

    int rowL = tid >> 2, qL = tid & 3;
    const __nv_bfloat16* gAh = g_xhi + ((size_t)n*CH + ci0 + rowL)*HW + qL*16;
    const __nv_bfloat16* gAl = g_xlo + ((size_t)n*CH + ci0 + rowL)*HW + qL*16;
    const __nv_bfloat16* gBh = g_xhi + ((size_t)n*CH + cj0 + rowL)*HW + qL*16;
    const __nv_bfloat16* gBl = g_xlo + ((size_t)n*CH + cj0 + rowL)*HW + qL*16;

    float acc[2][4][4];
    #pragma unroll
    for (int a = 0; a < 2; a++)
        #pragma unroll
        for (int b = 0; b < 4; b++)
            #pragma unroll
            for (int k = 0; k < 4; k++) acc[a][b][k] = 0.f;

    auto prefetch = [&](int kb, int st) {
        uint32_t sb = sbase + st*GSTAGE;
        int pb = kb*64;
        uint32_t dA = sb + rowL*144 + qL*32;
        cp16(dA,           gAh + pb);
        cp16(dA + 16,      gAh + pb + 8);
        cp16(dA + GT,      gAl + pb);
        cp16(dA + GT + 16, gAl + pb + 8);
        if (!diag) {
            uint32_t dB = dA + 2*GT;
            cp16(dB,           gBh + pb);
            cp16(dB + 16,      gBh + pb + 8);
            cp16(dB + GT,      gBl + pb);
            cp16(dB + GT + 16, gBl + pb + 8);
        }
    };

    prefetch(0, 0); cp_commit();
    prefetch(1, 1); cp_commit();
    for (int kb = 0; kb < 16; kb++) {
        int cur = kb % 3;
        if (kb < 15) cp_wait<1>(); else cp_wait<0>();
        __syncthreads();
        if (kb + 2 < 16) { prefetch(kb+2, (kb+2) % 3); cp_commit(); }
        uint32_t sb = sbase + cur*GSTAGE;
        uint32_t bb = sb + (diag ? 0 : 2*GT);
        #pragma unroll
        for (int ks = 0; ks < 4; ks++) {
            int k0 = ks*16;
            uint32_t ah[2][4], al[2][4], bh[4][2], bl[4][2];
            int ar = lane & 15, ac = (lane >> 4) * 8;
            #pragma unroll
            for (int mt = 0; mt < 2; mt++) {
                uint32_t ao = sb + (wm*32 + mt*16 + ar)*144 + (k0 + ac)*2;
                ldm_x4(ah[mt], ao);
                ldm_x4(al[mt], ao + GT);
            }
            int br = lane & 7, bc = ((lane >> 3) & 1) * 8;
            #pragma unroll
            for (int nt = 0; nt < 4; nt++) {
                uint32_t bo = bb + (wn*32 + nt*8 + br)*144 + (k0 + bc)*2;
                ldm_x2(bh[nt], bo);
                ldm_x2(bl[nt], bo + GT);
            }
            #pragma unroll
            for (int mt = 0; mt < 2; mt++)
                #pragma unroll
                for (int nt = 0; nt < 4; nt++) {
                    mma_bf16(acc[mt][nt], ah[mt], bh[nt]);
                    mma_bf16(acc[mt][nt], ah[mt], bl[nt]);
                    mma_bf16(acc[mt][nt], al[mt], bh[nt]);
                }
        }
    }
    float* pout = g_part + ((size_t)q*64 + n)*16384;
    int rg = lane >> 2, cg = (lane & 3)*2;
    #pragma unroll
    for (int mt = 0; mt < 2; mt++)
        #pragma unroll
        for (int nt = 0; nt < 4; nt++) {
            int r0 = wm*32 + mt*16 + rg, c0 = wn*32 + nt*8 + cg;
            *(float2*)(pout + r0*128 + c0)     = make_float2(acc[mt][nt][0], acc[mt][nt][1]);
            *(float2*)(pout + (r0+8)*128 + c0) = make_float2(acc[mt][nt][2], acc[mt][nt][3]);
        }
}

// ---------------- pipelined tensor tile matmul for the solver (3-stage, 256 thr) ----------------
template<int TM>
__device__ __forceinline__ void nt_mm2(
    const __nv_bfloat16* __restrict__ Ah, const __nv_bfloat16* __restrict__ Al,
    const __nv_bfloat16* __restrict__ Bh, const __nv_bfloat16* __restrict__ Bl,
    __nv_bfloat16* __restrict__ Chi, __nv_bfloat16* __restrict__ Clo,
    int tr, int tc, int mode, float snorm, __nv_bfloat16* ns)
{
    constexpr int SA  = TM*72;
    constexpr int SB  = 64*40;
    constexpr int STB = (2*SA + 2*SB)*2;
    constexpr int NT  = (TM == 64) ? 2 : 1;
    constexpr int WNW = (TM == 64) ? 16 : 8;
    int tid = threadIdx.x, lane = tid & 31, wid = tid >> 5;
    int wm = (TM == 64) ? (wid >> 1) : (wid >> 2);
    int wn = (TM == 64) ? (wid & 1)  : (wid & 3);
    uint32_t base = smem_u32(ns);

    float acc[NT][4];
    #pragma unroll
    for (int nt = 0; nt < NT; nt++)
        #pragma unroll
        for (int k = 0; k < 4; k++) acc[nt][k] = 0.f;

    int brow = tid >> 2, bcol = tid & 3;

    auto stage = [&](int kb, int st) {
        uint32_t sb = base + st*STB;
        #pragma unroll
        for (int c = 0; c < TM*8; c += 256) {
            int cc = c + tid;
            int row = cc >> 3, col = cc & 7;
            uint32_t d = sb + row*144 + col*16;
            cp16(d,        Ah + (tr + row)*256 + kb + col*8);
            cp16(d + SA*2, Al + (tr + row)*256 + kb + col*8);
        }
        uint32_t dB = sb + 2*(SA*2) + brow*80 + bcol*16;
        cp16(dB,        Bh + (kb + brow)*256 + tc + bcol*8);
        cp16(dB + SB*2, Bl + (kb + brow)*256 + tc + bcol*8);
    };

    stage(0, 0); cp_commit();
    stage(64, 1); cp_commit();
    for (int kb = 0; kb < 4; kb++) {
        int cur = kb % 3;
        if (kb < 3) cp_wait<1>(); else cp_wait<0>();
        __syncthreads();
        if (kb + 2 < 4) { stage((kb+2)*64, (kb+2) % 3); cp_commit(); }
        uint32_t sb  = base + cur*STB;
        uint32_t sbB = sb + 2*(SA*2);
        #pragma unroll
        for (int ks = 0; ks < 4; ks++) {
            int k0 = ks*16;
            uint32_t ah[4], al[4], bh[NT][2], bl[NT][2];
            uint32_t ao = sb + (wm*16 + (lane & 15))*144 + (k0 + (lane >> 4)*8)*2;
            ldm_x4(ah, ao);
            ldm_x4(al, ao + SA*2);
            #pragma unroll
            for (int nt = 0; nt < NT; nt++) {
                uint32_t bo = sbB + (k0 + (lane & 15))*80 + (wn*WNW + nt*8)*2;
                ldm_x2t(bh[nt], bo);
                ldm_x2t(bl[nt], bo + SB*2);
            }
            #pragma unroll
            for (int nt = 0; nt < NT; nt++) {
                mma_bf16(acc[nt], ah, bh[nt]);
                mma_bf16(acc[nt], ah, bl[nt]);
                mma_bf16(acc[nt], al, bh[nt]);
            }
        }
    }
    int rg = lane >> 2, cg = (lane & 3)*2;
    #pragma unroll
    for (int nt = 0; nt < NT; nt++) {
        int col = tc + wn*WNW + nt*8 + cg;
        #pragma unroll
        for (int half = 0; half < 2; half++) {
            int row = tr + wm*16 + rg + half*8;
            float v0 = acc[nt][half*2], v1 = acc[nt][half*2+1];
            int idx = row*256 + col;
            if (mode == 1) {
                __nv_bfloat162 ph = *(__nv_bfloat162*)(g_Phi + idx);
                __nv_bfloat162 pl = *(__nv_bfloat162*)(g_Plo + idx);
                float p0 = __bfloat162float(ph.x) + __bfloat162float(pl.x);
                float p1 = __bfloat162float(ph.y) + __bfloat162float(pl.y);
                v0 = 1.5f*p0 - 0.5f*v0;
                v1 = 1.5f*p1 - 0.5f*v1;
            } else if (mode == 2) {
                v0 *= snorm; v1 *= snorm;
                *(float2*)(g_M + idx) = make_float2(v0, v1);
            }
            __nv_bfloat16 h0, l0, h1, l1;
            bfsplit(v0, h0, l0); bfsplit(v1, h1, l1);
            *(__nv_bfloat162*)(Chi + idx) = __nv_bfloat162(h0, h1);
            *(__nv_bfloat162*)(Clo + idx) = __nv_bfloat162(l0, l1);
        }
    }
}

#define SOLVER_SMEM (3*((2*64*72 + 2*64*40)*2))

// ---------------- persistent solver ----------------
__global__ void __launch_bounds__(256) k_solver(const float* __restrict__ rot) {
    extern __shared__ __align__(16) char dynsm[];
    __nv_bfloat16* ns = (__nv_bfloat16*)dynsm;
    int cta = blockIdx.x, tid = threadIdx.x, lane = tid & 31, wid = tid >> 5;
    __shared__ float red[256];
    __shared__ float s_scal[2];
    GBar gb;

    // phase 0: mean reduce
    {
        int wg = cta*8 + wid;
        if (wg < 256) {
            float s = g_msum[wg*NBATCH + lane] + g_msum[wg*NBATCH + 32 + lane];
            #pragma unroll
            for (int o = 16; o > 0; o >>= 1) s += __shfl_xor_sync(~0u, s, o);
            if (lane == 0) g_mean[wg] = s * (1.f / (float)MTOT);
        }
    }
    gbar(gb);

    // phase 1: sigfin
    {
        int idx4 = cta*256 + tid;
        int a = idx4 >> 6, b = (idx4 & 63) * 4;
        float4 s4 = make_float4(0.f, 0.f, 0.f, 0.f);
        if (a < 128 || b >= 128) {
            int q = (a < 128) ? ((b < 128) ? 0 : 1) : 2;
            const float* pp = g_part + (size_t)q*64*16384 + (a & 127)*128 + (b & 127);
            #pragma unroll 4
            for (int t = 0; t < 64; t++) {
                float4 v = __ldcg((const float4*)(pp + (size_t)t*16384));
                s4.x += v.x; s4.y += v.y; s4.z += v.z; s4.w += v.w;
            }
        } else {
            const float* pp = g_part + (size_t)1*64*16384 + b*128 + (a - 128);
            #pragma unroll 4
            for (int t = 0; t < 64; t++) {
                const float* bb = pp + (size_t)t*16384;
                s4.x += __ldcg(bb); s4.y += __ldcg(bb+128); s4.z += __ldcg(bb+256); s4.w += __ldcg(bb+384);
            }
        }
        float ma = g_mean[a];
        float4 mb = *(const float4*)(g_mean + b);
        float4 v = make_float4(s4.x*(1.f/(float)MTOT) - ma*mb.x,
                               s4.y*(1.f/(float)MTOT) - ma*mb.y,
                               s4.z*(1.f/(float)MTOT) - ma*mb.z,
                               s4.w*(1.f/(float)MTOT) - ma*mb.w);
        if (a == b)   v.x += EPSV;
        if (a == b+1) v.y += EPSV;
        if (a == b+2) v.z += EPSV;
        if (a == b+3) v.w += EPSV;
        *(float4*)(g_Sig + a*256 + b) = v;
    }
    gbar(gb);

    // phase 2: trace + init SigN hi/lo, P = I hi/lo, rot hi/lo
    {
        red[tid] = __ldcg(g_Sig + tid*257);
        __syncthreads();
        for (int o = 128; o > 0; o >>= 1) { if (tid < o) red[tid] += red[tid+o]; __syncthreads(); }
        if (tid == 0) { float tr = red[0]; s_scal[0] = 1.f/tr; s_scal[1] = sqrtf(1.f/tr); }
        __syncthreads();
        float sc = s_scal[0];
        int base = cta*1024 + tid*4;
        float4 sg = __ldcg((const float4*)(g_Sig + base));
        float4 rr = __ldcg((const float4*)(rot + base));
        int r = base >> 8, c = base & 255;
        float sv[4] = {sg.x*sc, sg.y*sc, sg.z*sc, sg.w*sc};
        float rv[4] = {rr.x, rr.y, rr.z, rr.w};
        __nv_bfloat16 sh[4], sl[4], rh[4], rl[4], ph[4], pl[4];
        #pragma unroll
        for (int k = 0; k < 4; k++) {
            bfsplit(sv[k], sh[k], sl[k]);
            bfsplit(rv[k], rh[k], rl[k]);
            ph[k] = __float2bfloat16((r == c + k) ? 1.f : 0.f);
            pl[k] = __float2bfloat16(0.f);
        }
        *(__nv_bfloat162*)(g_SNhi + base)     = __nv_bfloat162(sh[0], sh[1]);
        *(__nv_bfloat162*)(g_SNhi + base + 2) = __nv_bfloat162(sh[2], sh[3]);
        *(__nv_bfloat162*)(g_SNlo + base)     = __nv_bfloat162(sl[0], sl[1]);
        *(__nv_bfloat162*)(g_SNlo + base + 2) = __nv_bfloat162(sl[2], sl[3]);
        *(__nv_bfloat162*)(g_Rhi + base)      = __nv_bfloat162(rh[0], rh[1]);
        *(__nv_bfloat162*)(g_Rhi + base + 2)  = __nv_bfloat162(rh[2], rh[3]);
        *(__nv_bfloat162*)(g_Rlo + base)      = __nv_bfloat162(rl[0], rl[1]);
        *(__nv_bfloat162*)(g_Rlo + base + 2)  = __nv_bfloat162(rl[2], rl[3]);
        *(__nv_bfloat162*)(g_Phi + base)      = __nv_bfloat162(ph[0], ph[1]);
        *(__nv_bfloat162*)(g_Phi + base + 2)  = __nv_bfloat162(ph[2], ph[3]);
        *(__nv_bfloat162*)(g_Plo + base)      = __nv_bfloat162(pl[0], pl[1]);
        *(__nv_bfloat162*)(g_Plo + base + 2)  = __nv_bfloat162(pl[2], pl[3]);
    }
    gbar(gb);

    // phase 3: Newton-Schulz on tensor cores — all 64 CTAs busy each phase
    for (int it = 0; it < T_ITERS; it++) {
        if (cta < 32) {
            int t = cta;
            nt_mm2<64>(g_Phi, g_Plo, g_Phi, g_Plo, g_T1hi, g_T1lo,
                       (t >> 3)*64, (t & 7)*32, 0, 0.f, ns);
        } else {
            int t = cta - 32;
            nt_mm2<64>(g_Phi, g_Plo, g_SNhi, g_SNlo, g_T2hi, g_T2lo,
                       (t >> 3)*64, (t & 7)*32, 0, 0.f, ns);
        }
        gbar(gb);
        nt_mm2<32>(g_T1hi, g_T1lo, g_T2hi, g_T2lo, g_Phi, g_Plo,
                   (cta >> 3)*32, (cta & 7)*32, 1, 0.f, ns);
        gbar(gb);
    }

    // phase 4: M = s * rot * P
    nt_mm2<32>(g_Rhi, g_Rlo, g_Phi, g_Plo, g_Mhi, g_Mlo,
               (cta >> 3)*32, (cta & 7)*32, 2, s_scal[1], ns);
    gbar(gb);

    // phase 5: bias
    {
        int wg = cta*8 + wid;
        if (wg < 256) {
            float s = 0.f;
            #pragma unroll
            for (int k = 0; k < 8; k++)
                s += __ldcg(g_M + wg*256 + lane + k*32) * g_mean[lane + k*32];
            #pragma unroll
            for (int o = 16; o > 0; o >>= 1) s += __shfl_xor_sync(~0u, s, o);
            if (lane == 0) g_bias[wg] = s;
        }
    }
}

// ---------------- output GEMM, 3-stage cp.async, 512 threads ----------------
#define OAT 18432u
#define OBT 17408u
#define OBOFF (2u*OAT)
#define OSTAGE (2u*OAT + 2u*OBT)
#define OUT_SMEM (3*OSTAGE)
__global__ void __launch_bounds__(512, 1) k_out_mma(float* __restrict__ out) {
    extern __shared__ char sm[];
    int p0 = blockIdx.x*128, d0 = blockIdx.y*128, n = blockIdx.z;
    int tid = threadIdx.x, lane = tid & 31, wid = tid >> 5;
    int wm = wid >> 2, wn = wid & 3;        // 4 x 4 warps, 32x32 tiles
    uint32_t sbase = smem_u32(sm);

    int rowA = tid >> 2, qA = tid & 3;
    int rowB = tid >> 3, qB = tid & 7;
    const __nv_bfloat16* gMh = g_Mhi + (d0 + rowA)*256 + qA*16;
    const __nv_bfloat16* gMl = g_Mlo + (d0 + rowA)*256 + qA*16;
    const __nv_bfloat16* gXh = g_xhi + ((size_t)n*CH + rowB)*HW + p0 + qB*16;
    const __nv_bfloat16* gXl = g_xlo + ((size_t)n*CH + rowB)*HW + p0 + qB*16;

    float acc[2][4][4];
    #pragma unroll
    for (int a = 0; a < 2; a++)
        #pragma unroll
        for (int b = 0; b < 4; b++)
            #pragma unroll
            for (int k = 0; k < 4; k++) acc[a][b][k] = 0.f;

    auto prefetch = [&](int cbi, int st) {
        uint32_t sb = sbase + st*OSTAGE;
        int cb = cbi*64;
        uint32_t dA = sb + rowA*144 + qA*32;
        cp16(dA,            gMh + cb);
        cp16(dA + 16,       gMh + cb + 8);
        cp16(dA + OAT,      gMl + cb);
        cp16(dA + OAT + 16, gMl + cb + 8);
        uint32_t dB = sb + OBOFF + rowB*272 + qB*32;
        size_t go = (size_t)cb*HW;
        cp16(dB,            gXh + go);
        cp16(dB + 16,       gXh + go + 8);
        cp16(dB + OBT,      gXl + go);
        cp16(dB + OBT + 16, gXl + go + 8);
    };

    prefetch(0, 0); cp_commit();
    prefetch(1, 1); cp_commit();
    for (int cbi = 0; cbi < 4; cbi++) {
        int cur = cbi % 3;
        if (cbi < 3) cp_wait<1>(); else cp_wait<0>();
        __syncthreads();
        if (cbi + 2 < 4) { prefetch(cbi+2, (cbi+2) % 3); cp_commit(); }
        uint32_t sb = sbase + cur*OSTAGE;
        #pragma unroll
        for (int ks = 0; ks < 4; ks++) {
            int k0 = ks*16;
            uint32_t ah[2][4], al[2][4], bh[4][2], bl[4][2];
            int ar = lane & 15, ac = (lane >> 4) * 8;
            #pragma unroll
            for (int mt = 0; mt < 2; mt++) {
                uint32_t ao = sb + (wm*32 + mt*16 + ar)*144 + (k0 + ac)*2;
                ldm_x4(ah[mt], ao);
                ldm_x4(al[mt], ao + OAT);
            }
            int br = lane & 15;
            #pragma unroll
            for (int nt = 0; nt < 4; nt++) {
                uint32_t bo = sb + OBOFF + (k0 + br)*272 + (wn*32 + nt*8)*2;
                ldm_x2t(bh[nt], bo);
                ldm_x2t(bl[nt], bo + OBT);
            }
            #pragma unroll
            for (int mt = 0; mt < 2; mt++)
                #pragma unroll
                for (int nt = 0; nt < 4; nt++) {
                    mma_bf16(acc[mt][nt], ah[mt], bh[nt]);
                    mma_bf16(acc[mt][nt], ah[mt], bl[nt]);
                    mma_bf16(acc[mt][nt], al[mt], bh[nt]);
                }
        }
    }
    float* On = out + (size_t)n * (CH*HW);
    int rg = lane >> 2, cg = (lane & 3)*2;
    #pragma unroll
    for (int mt = 0; mt < 2; mt++) {
        int d = d0 + wm*32 + mt*16 + rg;
        float b0 = g_bias[d], b1 = g_bias[d+8];
        #pragma unroll
        for (int nt = 0; nt < 4; nt++) {
            int p = p0 + wn*32 + nt*8 + cg;
            *(float2*)(On + (size_t)d*HW + p)     = make_float2(acc[mt][nt][0]-b0, acc[mt][nt][1]-b0);
            *(float2*)(On + (size_t)(d+8)*HW + p) = make_float2(acc[mt][nt][2]-b1, acc[mt][nt][3]-b1);
        }
    }
}

// ---------------- launch ----------------
extern "C" void kernel_launch(void* const* d_in, const int* in_sizes, int n_in,
                              void* d_out, int out_size) {
    const float* X   = (const float*)d_in[0];
    const float* rot = (const float*)d_in[1];
    if (n_in >= 2 && in_sizes[0] == CH*CH && in_sizes[1] != CH*CH) {
        X = (const float*)d_in[1]; rot = (const float*)d_in[0];
    }
    float* out = (float*)d_out;
    (void)out_size;

    cudaFuncSetAttribute(k_gram_mma, cudaFuncAttributeMaxDynamicSharedMemorySize, GRAM_SMEM);
    cudaFuncSetAttribute(k_out_mma,  cudaFuncAttributeMaxDynamicSharedMemorySize, OUT_SMEM);
    cudaFuncSetAttribute(k_solver,   cudaFuncAttributeMaxDynamicSharedMemorySize, SOLVER_SMEM);

    k_conv1<<<dim3(256, 64), 256>>>(X);
    k_gram_mma<<<dim3(3, 64), 512, GRAM_SMEM>>>();
    k_solver<<<NCTA, 256, SOLVER_SMEM>>>(rot);
    k_out_mma<<<dim3(8, 2, 64), 512, OUT_SMEM>>>(out);
}

// round 13
// speedup vs baseline: 1.5357x; 1.0101x over previous
#include <cuda_runtime.h>
#include <cuda_bf16.h>
#include <math.h>
#include <stdint.h>

#define CH 256
#define NBATCH 64
#define HW 1024
#define MTOT 65536
#define EPSV 1e-5f
#define T_ITERS 10
#define NCTA 64

// ---------------- device scratch (16B-aligned: float4/cp.async access) ----------------
__device__ float g_mean[CH];
__device__ float g_msum[CH*NBATCH];
__device__ float g_bias[CH];
__device__ float g_Sig [CH*CH];
__device__ float g_M   [CH*CH];
__device__ float g_part[192*16384];
__device__ __align__(16) __nv_bfloat16 g_xhi[64L*256*1024];
__device__ __align__(16) __nv_bfloat16 g_xlo[64L*256*1024];
__device__ __align__(16) __nv_bfloat16 g_Mhi [CH*CH], g_Mlo [CH*CH];
__device__ __align__(16) __nv_bfloat16 g_Phi [CH*CH], g_Plo [CH*CH];
__device__ __align__(16) __nv_bfloat16 g_T1hi[CH*CH], g_T1lo[CH*CH];
__device__ __align__(16) __nv_bfloat16 g_T2hi[CH*CH], g_T2lo[CH*CH];
__device__ __align__(16) __nv_bfloat16 g_SNhi[CH*CH], g_SNlo[CH*CH];
__device__ __align__(16) __nv_bfloat16 g_Rhi [CH*CH], g_Rlo [CH*CH];
__device__ unsigned g_bar_cnt;

// ---------------- helpers ----------------
__device__ __forceinline__ uint32_t smem_u32(const void* p) {
    uint32_t a;
    asm("{ .reg .u64 t; cvta.to.shared.u64 t, %1; cvt.u32.u64 %0, t; }" : "=r"(a) : "l"(p));
    return a;
}
__device__ __forceinline__ void ldm_x4(uint32_t* r, uint32_t addr) {
    asm volatile("ldmatrix.sync.aligned.m8n8.x4.shared.b16 {%0,%1,%2,%3}, [%4];"
        : "=r"(r[0]), "=r"(r[1]), "=r"(r[2]), "=r"(r[3]) : "r"(addr));
}
__device__ __forceinline__ void ldm_x2(uint32_t* r, uint32_t addr) {
    asm volatile("ldmatrix.sync.aligned.m8n8.x2.shared.b16 {%0,%1}, [%2];"
        : "=r"(r[0]), "=r"(r[1]) : "r"(addr));
}
__device__ __forceinline__ void ldm_x2t(uint32_t* r, uint32_t addr) {
    asm volatile("ldmatrix.sync.aligned.m8n8.x2.trans.shared.b16 {%0,%1}, [%2];"
        : "=r"(r[0]), "=r"(r[1]) : "r"(addr));
}
__device__ __forceinline__ void mma_bf16(float* c, const uint32_t* a, const uint32_t* b) {
    asm volatile("mma.sync.aligned.m16n8k16.row.col.f32.bf16.bf16.f32 "
        "{%0,%1,%2,%3}, {%4,%5,%6,%7}, {%8,%9}, {%0,%1,%2,%3};"
        : "+f"(c[0]), "+f"(c[1]), "+f"(c[2]), "+f"(c[3])
        : "r"(a[0]), "r"(a[1]), "r"(a[2]), "r"(a[3]), "r"(b[0]), "r"(b[1]));
}
__device__ __forceinline__ void cp16(uint32_t dst, const void* src) {
    asm volatile("cp.async.cg.shared.global [%0], [%1], 16;" :: "r"(dst), "l"(src));
}
__device__ __forceinline__ void cp_commit() { asm volatile("cp.async.commit_group;" ::: "memory"); }
template<int N> __device__ __forceinline__ void cp_wait() {
    asm volatile("cp.async.wait_group %0;" :: "n"(N) : "memory");
}
__device__ __forceinline__ void bfsplit(float v, __nv_bfloat16& h, __nv_bfloat16& l) {
    h = __float2bfloat16(v);
    l = __float2bfloat16(v - __bfloat162float(h));
}

// ---------------- monotonic grid barrier: release/acquire ----------------
struct GBar { unsigned nbar = 0; };
__device__ __forceinline__ void gbar(GBar& gb) {
    __syncthreads();
    gb.nbar++;
    if (threadIdx.x == 0) {
        unsigned target = gb.nbar * NCTA;
        asm volatile("red.release.gpu.add.u32 [%0], 1;" :: "l"(&g_bar_cnt) : "memory");
        unsigned v;
        do {
            asm volatile("ld.acquire.gpu.u32 %0, [%1];" : "=r"(v) : "l"(&g_bar_cnt) : "memory");
        } while (v < target);
    }
    __syncthreads();
}

// ---------------- convert X -> bf16 hi/lo + per-(c,n) sums (+ barrier counter reset) ----------------
__global__ void __launch_bounds__(256) k_conv1(const float* __restrict__ X) {
    int c = blockIdx.x, n = blockIdx.y, t = threadIdx.x;
    if (c == 0 && n == 0 && t == 0) g_bar_cnt = 0;
    size_t base = ((size_t)n*CH + c) * HW;
    float4 v = *(const float4*)(X + base + t*4);
    float f[4] = {v.x, v.y, v.z, v.w};
    __nv_bfloat16 h[4], l[4];
    #pragma unroll
    for (int k = 0; k < 4; k++) bfsplit(f[k], h[k], l[k]);
    __nv_bfloat162* ph = (__nv_bfloat162*)(g_xhi + base);
    __nv_bfloat162* pl = (__nv_bfloat162*)(g_xlo + base);
    ph[t*2]   = __nv_bfloat162(h[0], h[1]);
    ph[t*2+1] = __nv_bfloat162(h[2], h[3]);
    pl[t*2]   = __nv_bfloat162(l[0], l[1]);
    pl[t*2+1] = __nv_bfloat162(l[2], l[3]);
    float s = f[0] + f[1] + f[2] + f[3];
    __shared__ float sm[256];
    sm[t] = s; __syncthreads();
    for (int o = 128; o > 0; o >>= 1) { if (t < o) sm[t] += sm[t+o]; __syncthreads(); }
    if (t == 0) g_msum[c*NBATCH + n] = sm[0];
}

// ---------------- Gram: quadrants x 64 n-splits, 3-stage cp.async, 512 threads ----------------
#define GT 18432u
#define GSTAGE (4u*GT)
#define GRAM_SMEM (3*GSTAGE)
__global__ void __launch_bounds__(512, 1) k_gram_mma() {
    extern __shared__ char sm[];
    int q = blockIdx.x, n = blockIdx.y;
    int ci0 = (q == 2) ? 128 : 0;
    int cj0 = (q == 0) ? 0 : 128;
    bool diag = (q != 1);
    int tid = threadIdx.x, lane = tid & 31, wid = tid >> 5;
    int wm = wid >> 2, wn = wid & 3;
    uint32_t sbase = smem_u32(sm);

    int rowL = tid >> 2, qL = tid & 3;
    const __nv_bfloat16* gAh = g_xhi + ((size_t)n*CH + ci0 + rowL)*HW + qL*16;
    const __nv_bfloat16* gAl = g_xlo + ((size_t)n*CH + ci0 + rowL)*HW + qL*16;
    const __nv_bfloat16* gBh = g_xhi + ((size_t)n*CH + cj0 + rowL)*HW + qL*16;
    const __nv_bfloat16* gBl = g_xlo + ((size_t)n*CH + cj0 + rowL)*HW + qL*16;

    float acc[2][4][4];
    #pragma unroll
    for (int a = 0; a < 2; a++)
        #pragma unroll
        for (int b = 0; b < 4; b++)
            #pragma unroll
            for (int k = 0; k < 4; k++) acc[a][b][k] = 0.f;

    auto prefetch = [&](int kb, int st) {
        uint32_t sb = sbase + st*GSTAGE;
        int pb = kb*64;
        uint32_t dA = sb + rowL*144 + qL*32;
        cp16(dA,           gAh + pb);
        cp16(dA + 16,      gAh + pb + 8);
        cp16(dA + GT,      gAl + pb);
        cp16(dA + GT + 16, gAl + pb + 8);
        if (!diag) {
            uint32_t dB = dA + 2*GT;
            cp16(dB,           gBh + pb);
            cp16(dB + 16,      gBh + pb + 8);
            cp16(dB + GT,      gBl + pb);
            cp16(dB + GT + 16, gBl + pb + 8);
        }
    };

    prefetch(0, 0); cp_commit();
    prefetch(1, 1); cp_commit();
    for (int kb = 0; kb < 16; kb++) {
        int cur = kb % 3;
        if (kb < 15) cp_wait<1>(); else cp_wait<0>();
        __syncthreads();
        if (kb + 2 < 16) { prefetch(kb+2, (kb+2) % 3); cp_commit(); }
        uint32_t sb = sbase + cur*GSTAGE;
        uint32_t bb = sb + (diag ? 0 : 2*GT);
        #pragma unroll
        for (int ks = 0; ks < 4; ks++) {
            int k0 = ks*16;
            uint32_t ah[2][4], al[2][4], bh[4][2], bl[4][2];
            int ar = lane & 15, ac = (lane >> 4) * 8;
            #pragma unroll
            for (int mt = 0; mt < 2; mt++) {
                uint32_t ao = sb + (wm*32 + mt*16 + ar)*144 + (k0 + ac)*2;
                ldm_x4(ah[mt], ao);
                ldm_x4(al[mt], ao + GT);
            }
            int br = lane & 7, bc = ((lane >> 3) & 1) * 8;
            #pragma unroll
            for (int nt = 0; nt < 4; nt++) {
                uint32_t bo = bb + (wn*32 + nt*8 + br)*144 + (k0 + bc)*2;
                ldm_x2(bh[nt], bo);
                ldm_x2(bl[nt], bo + GT);
            }
            #pragma unroll
            for (int mt = 0; mt < 2; mt++)
                #pragma unroll
                for (int nt = 0; nt < 4; nt++) {
                    mma_bf16(acc[mt][nt], ah[mt], bh[nt]);
                    mma_bf16(acc[mt][nt], ah[mt], bl[nt]);
                    mma_bf16(acc[mt][nt], al[mt], bh[nt]);
                }
        }
    }
    float* pout = g_part + ((size_t)q*64 + n)*16384;
    int rg = lane >> 2, cg = (lane & 3)*2;
    #pragma unroll
    for (int mt = 0; mt < 2; mt++)
        #pragma unroll
        for (int nt = 0; nt < 4; nt++) {
            int r0 = wm*32 + mt*16 + rg, c0 = wn*32 + nt*8 + cg;
            *(float2*)(pout + r0*128 + c0)     = make_float2(acc[mt][nt][0], acc[mt][nt][1]);
            *(float2*)(pout + (r0+8)*128 + c0) = make_float2(acc[mt][nt][2], acc[mt][nt][3]);
        }
}

// ---------------- pipelined tensor tile matmul for the solver (3-stage, 256 thr) ----------------
template<int TM>
__device__ __forceinline__ void nt_mm2(
    const __nv_bfloat16* __restrict__ Ah, const __nv_bfloat16* __restrict__ Al,
    const __nv_bfloat16* __restrict__ Bh, const __nv_bfloat16* __restrict__ Bl,
    __nv_bfloat16* __restrict__ Chi, __nv_bfloat16* __restrict__ Clo,
    int tr, int tc, int mode, float snorm, __nv_bfloat16* ns)
{
    constexpr int SA  = TM*72;
    constexpr int SB  = 64*40;
    constexpr int STB = (2*SA + 2*SB)*2;
    constexpr int NT  = (TM == 64) ? 2 : 1;
    constexpr int WNW = (TM == 64) ? 16 : 8;
    int tid = threadIdx.x, lane = tid & 31, wid = tid >> 5;
    int wm = (TM == 64) ? (wid >> 1) : (wid >> 2);
    int wn = (TM == 64) ? (wid & 1)  : (wid & 3);
    uint32_t base = smem_u32(ns);

    float acc[NT][4];
    #pragma unroll
    for (int nt = 0; nt < NT; nt++)
        #pragma unroll
        for (int k = 0; k < 4; k++) acc[nt][k] = 0.f;

    int brow = tid >> 2, bcol = tid & 3;

    auto stage = [&](int kb, int st) {
        uint32_t sb = base + st*STB;
        #pragma unroll
        for (int c = 0; c < TM*8; c += 256) {
            int cc = c + tid;
            int row = cc >> 3, col = cc & 7;
            uint32_t d = sb + row*144 + col*16;
            cp16(d,        Ah + (tr + row)*256 + kb + col*8);
            cp16(d + SA*2, Al + (tr + row)*256 + kb + col*8);
        }
        uint32_t dB = sb + 2*(SA*2) + brow*80 + bcol*16;
        cp16(dB,        Bh + (kb + brow)*256 + tc + bcol*8);
        cp16(dB + SB*2, Bl + (kb + brow)*256 + tc + bcol*8);
    };

    stage(0, 0); cp_commit();
    stage(64, 1); cp_commit();
    for (int kb = 0; kb < 4; kb++) {
        int cur = kb % 3;
        if (kb < 3) cp_wait<1>(); else cp_wait<0>();
        __syncthreads();
        if (kb + 2 < 4) { stage((kb+2)*64, (kb+2) % 3); cp_commit(); }
        uint32_t sb  = base + cur*STB;
        uint32_t sbB = sb + 2*(SA*2);
        #pragma unroll
        for (int ks = 0; ks < 4; ks++) {
            int k0 = ks*16;
            uint32_t ah[4], al[4], bh[NT][2], bl[NT][2];
            uint32_t ao = sb + (wm*16 + (lane & 15))*144 + (k0 + (lane >> 4)*8)*2;
            ldm_x4(ah, ao);
            ldm_x4(al, ao + SA*2);
            #pragma unroll
            for (int nt = 0; nt < NT; nt++) {
                uint32_t bo = sbB + (k0 + (lane & 15))*80 + (wn*WNW + nt*8)*2;
                ldm_x2t(bh[nt], bo);
                ldm_x2t(bl[nt], bo + SB*2);
            }
            #pragma unroll
            for (int nt = 0; nt < NT; nt++) {
                mma_bf16(acc[nt], ah, bh[nt]);
                mma_bf16(acc[nt], ah, bl[nt]);
                mma_bf16(acc[nt], al, bh[nt]);
            }
        }
    }
    int rg = lane >> 2, cg = (lane & 3)*2;
    #pragma unroll
    for (int nt = 0; nt < NT; nt++) {
        int col = tc + wn*WNW + nt*8 + cg;
        #pragma unroll
        for (int half = 0; half < 2; half++) {
            int row = tr + wm*16 + rg + half*8;
            float v0 = acc[nt][half*2], v1 = acc[nt][half*2+1];
            int idx = row*256 + col;
            if (mode == 1) {
                __nv_bfloat162 ph = *(__nv_bfloat162*)(g_Phi + idx);
                __nv_bfloat162 pl = *(__nv_bfloat162*)(g_Plo + idx);
                float p0 = __bfloat162float(ph.x) + __bfloat162float(pl.x);
                float p1 = __bfloat162float(ph.y) + __bfloat162float(pl.y);
                v0 = 1.5f*p0 - 0.5f*v0;
                v1 = 1.5f*p1 - 0.5f*v1;
            } else if (mode == 2) {
                v0 *= snorm; v1 *= snorm;
                *(float2*)(g_M + idx) = make_float2(v0, v1);
            }
            __nv_bfloat16 h0, l0, h1, l1;
            bfsplit(v0, h0, l0); bfsplit(v1, h1, l1);
            *(__nv_bfloat162*)(Chi + idx) = __nv_bfloat162(h0, h1);
            *(__nv_bfloat162*)(Clo + idx) = __nv_bfloat162(l0, l1);
        }
    }
}

#define SOLVER_SMEM (3*((2*64*72 + 2*64*40)*2))

// ---------------- persistent solver ----------------
__global__ void __launch_bounds__(256) k_solver(const float* __restrict__ rot) {
    extern __shared__ __align__(16) char dynsm[];
    __nv_bfloat16* ns = (__nv_bfloat16*)dynsm;
    int cta = blockIdx.x, tid = threadIdx.x, lane = tid & 31, wid = tid >> 5;
    __shared__ float red[256];
    __shared__ float s_scal[2];
    GBar gb;

    // phase 0: mean reduce
    {
        int wg = cta*8 + wid;
        if (wg < 256) {
            float s = g_msum[wg*NBATCH + lane] + g_msum[wg*NBATCH + 32 + lane];
            #pragma unroll
            for (int o = 16; o > 0; o >>= 1) s += __shfl_xor_sync(~0u, s, o);
            if (lane == 0) g_mean[wg] = s * (1.f / (float)MTOT);
        }
    }
    gbar(gb);

    // phase 1: sigfin
    {
        int idx4 = cta*256 + tid;
        int a = idx4 >> 6, b = (idx4 & 63) * 4;
        float4 s4 = make_float4(0.f, 0.f, 0.f, 0.f);
        if (a < 128 || b >= 128) {
            int q = (a < 128) ? ((b < 128) ? 0 : 1) : 2;
            const float* pp = g_part + (size_t)q*64*16384 + (a & 127)*128 + (b & 127);
            #pragma unroll 4
            for (int t = 0; t < 64; t++) {
                float4 v = __ldcg((const float4*)(pp + (size_t)t*16384));
                s4.x += v.x; s4.y += v.y; s4.z += v.z; s4.w += v.w;
            }
        } else {
            const float* pp = g_part + (size_t)1*64*16384 + b*128 + (a - 128);
            #pragma unroll 4
            for (int t = 0; t < 64; t++) {
                const float* bb = pp + (size_t)t*16384;
                s4.x += __ldcg(bb); s4.y += __ldcg(bb+128); s4.z += __ldcg(bb+256); s4.w += __ldcg(bb+384);
            }
        }
        float ma = g_mean[a];
        float4 mb = *(const float4*)(g_mean + b);
        float4 v = make_float4(s4.x*(1.f/(float)MTOT) - ma*mb.x,
                               s4.y*(1.f/(float)MTOT) - ma*mb.y,
                               s4.z*(1.f/(float)MTOT) - ma*mb.z,
                               s4.w*(1.f/(float)MTOT) - ma*mb.w);
        if (a == b)   v.x += EPSV;
        if (a == b+1) v.y += EPSV;
        if (a == b+2) v.z += EPSV;
        if (a == b+3) v.w += EPSV;
        *(float4*)(g_Sig + a*256 + b) = v;
    }
    gbar(gb);

    // phase 2: trace + init SigN hi/lo, P = I hi/lo, rot hi/lo
    {
        red[tid] = __ldcg(g_Sig + tid*257);
        __syncthreads();
        for (int o = 128; o > 0; o >>= 1) { if (tid < o) red[tid] += red[tid+o]; __syncthreads(); }
        if (tid == 0) { float tr = red[0]; s_scal[0] = 1.f/tr; s_scal[1] = sqrtf(1.f/tr); }
        __syncthreads();
        float sc = s_scal[0];
        int base = cta*1024 + tid*4;
        float4 sg = __ldcg((const float4*)(g_Sig + base));
        float4 rr = __ldcg((const float4*)(rot + base));
        int r = base >> 8, c = base & 255;
        float sv[4] = {sg.x*sc, sg.y*sc, sg.z*sc, sg.w*sc};
        float rv[4] = {rr.x, rr.y, rr.z, rr.w};
        __nv_bfloat16 sh[4], sl[4], rh[4], rl[4], ph[4], pl[4];
        #pragma unroll
        for (int k = 0; k < 4; k++) {
            bfsplit(sv[k], sh[k], sl[k]);
            bfsplit(rv[k], rh[k], rl[k]);
            ph[k] = __float2bfloat16((r == c + k) ? 1.f : 0.f);
            pl[k] = __float2bfloat16(0.f);
        }
        *(__nv_bfloat162*)(g_SNhi + base)     = __nv_bfloat162(sh[0], sh[1]);
        *(__nv_bfloat162*)(g_SNhi + base + 2) = __nv_bfloat162(sh[2], sh[3]);
        *(__nv_bfloat162*)(g_SNlo + base)     = __nv_bfloat162(sl[0], sl[1]);
        *(__nv_bfloat162*)(g_SNlo + base + 2) = __nv_bfloat162(sl[2], sl[3]);
        *(__nv_bfloat162*)(g_Rhi + base)      = __nv_bfloat162(rh[0], rh[1]);
        *(__nv_bfloat162*)(g_Rhi + base + 2)  = __nv_bfloat162(rh[2], rh[3]);
        *(__nv_bfloat162*)(g_Rlo + base)      = __nv_bfloat162(rl[0], rl[1]);
        *(__nv_bfloat162*)(g_Rlo + base + 2)  = __nv_bfloat162(rl[2], rl[3]);
        *(__nv_bfloat162*)(g_Phi + base)      = __nv_bfloat162(ph[0], ph[1]);
        *(__nv_bfloat162*)(g_Phi + base + 2)  = __nv_bfloat162(ph[2], ph[3]);
        *(__nv_bfloat162*)(g_Plo + base)      = __nv_bfloat162(pl[0], pl[1]);
        *(__nv_bfloat162*)(g_Plo + base + 2)  = __nv_bfloat162(pl[2], pl[3]);
    }
    gbar(gb);

    // phase 3: Newton-Schulz on tensor cores — all 64 CTAs busy each phase
    for (int it = 0; it < T_ITERS; it++) {
        if (cta < 32) {
            int t = cta;
            nt_mm2<64>(g_Phi, g_Plo, g_Phi, g_Plo, g_T1hi, g_T1lo,
                       (t >> 3)*64, (t & 7)*32, 0, 0.f, ns);
        } else {
            int t = cta - 32;
            nt_mm2<64>(g_Phi, g_Plo, g_SNhi, g_SNlo, g_T2hi, g_T2lo,
                       (t >> 3)*64, (t & 7)*32, 0, 0.f, ns);
        }
        gbar(gb);
        nt_mm2<32>(g_T1hi, g_T1lo, g_T2hi, g_T2lo, g_Phi, g_Plo,
                   (cta >> 3)*32, (cta & 7)*32, 1, 0.f, ns);
        gbar(gb);
    }

    // phase 4: M = s * rot * P
    nt_mm2<32>(g_Rhi, g_Rlo, g_Phi, g_Plo, g_Mhi, g_Mlo,
               (cta >> 3)*32, (cta & 7)*32, 2, s_scal[1], ns);
    gbar(gb);

    // phase 5: bias
    {
        int wg = cta*8 + wid;
        if (wg < 256) {
            float s = 0.f;
            #pragma unroll
            for (int k = 0; k < 8; k++)
                s += __ldcg(g_M + wg*256 + lane + k*32) * g_mean[lane + k*32];
            #pragma unroll
            for (int o = 16; o > 0; o >>= 1) s += __shfl_xor_sync(~0u, s, o);
            if (lane == 0) g_bias[wg] = s;
        }
    }
}

// ---------------- persistent output GEMM: M resident in smem, X streamed ----------------
// 128 CTAs: cta&1 -> d-half, cta>>1 -> 8 (n,p0) combos. 32 rolling K-chunks of 64.
#define OMT 18432u                   // one M chunk (128 rows x 144B)
#define OMREG (8u*OMT)               // 4 chunks x hi/lo = 147456
#define OXT 17408u                   // X half-tile (64 x 272B)
#define OXSTAGE (2u*OXT)             // hi+lo = 34816
#define OUT_SMEM (OMREG + 2*OXSTAGE) // 217088
__global__ void __launch_bounds__(512, 1) k_out_mma(float* __restrict__ out) {
    extern __shared__ char sm[];
    int tid = threadIdx.x, lane = tid & 31, wid = tid >> 5;
    int wm = wid >> 2, wn = wid & 3;         // 4 x 4 warps, 32x32 warp tiles
    uint32_t sbase = smem_u32(sm);
    int cta = blockIdx.x;
    int d0 = (cta & 1) * 128;
    int combo0 = (cta >> 1) * 8;

    // load M panel: 4 K-chunks, hi/lo, resident for whole kernel
    int rowA = tid >> 2, qA = tid & 3;
    #pragma unroll
    for (int c = 0; c < 4; c++) {
        uint32_t dA = sbase + c*(2*OMT) + rowA*144 + qA*32;
        const __nv_bfloat16* mh = g_Mhi + (d0 + rowA)*256 + c*64 + qA*16;
        const __nv_bfloat16* ml = g_Mlo + (d0 + rowA)*256 + c*64 + qA*16;
        cp16(dA,            mh);
        cp16(dA + 16,       mh + 8);
        cp16(dA + OMT,      ml);
        cp16(dA + OMT + 16, ml + 8);
    }
    cp_commit();

    int rowB = tid >> 3, qB = tid & 7;
    auto stageX = [&](int g, int st) {
        int combo = combo0 + (g >> 2);
        int n = combo >> 3, p0 = (combo & 7) * 128;
        int cb = (g & 3) * 64;
        uint32_t dB = sbase + OMREG + st*OXSTAGE + rowB*272 + qB*32;
        const __nv_bfloat16* xh = g_xhi + ((size_t)n*CH + cb + rowB)*HW + p0 + qB*16;
        const __nv_bfloat16* xl = g_xlo + ((size_t)n*CH + cb + rowB)*HW + p0 + qB*16;
        cp16(dB,            xh);
        cp16(dB + 16,       xh + 8);
        cp16(dB + OXT,      xl);
        cp16(dB + OXT + 16, xl + 8);
    };

    stageX(0, 0); cp_commit();

    float acc[2][4][4];
    #pragma unroll
    for (int a = 0; a < 2; a++)
        #pragma unroll
        for (int b = 0; b < 4; b++)
            #pragma unroll
            for (int k = 0; k < 4; k++) acc[a][b][k] = 0.f;

    for (int g = 0; g < 32; g++) {
        int cur = g & 1;
        if (g < 31) { stageX(g+1, cur^1); cp_commit(); cp_wait<1>(); }
        else        { cp_wait<0>(); }
        __syncthreads();
        uint32_t sbM = sbase + (g & 3)*(2*OMT);
        uint32_t sbX = sbase + OMREG + cur*OXSTAGE;
        #pragma unroll
        for (int ks = 0; ks < 4; ks++) {
            int k0 = ks*16;
            uint32_t ah[2][4], al[2][4], bh[4][2], bl[4][2];
            int ar = lane & 15, ac = (lane >> 4) * 8;
            #pragma unroll
            for (int mt = 0; mt < 2; mt++) {
                uint32_t ao = sbM + (wm*32 + mt*16 + ar)*144 + (k0 + ac)*2;
                ldm_x4(ah[mt], ao);
                ldm_x4(al[mt], ao + OMT);
            }
            int br = lane & 15;
            #pragma unroll
            for (int nt = 0; nt < 4; nt++) {
                uint32_t bo = sbX + (k0 + br)*272 + (wn*32 + nt*8)*2;
                ldm_x2t(bh[nt], bo);
                ldm_x2t(bl[nt], bo + OXT);
            }
            #pragma unroll
            for (int mt = 0; mt < 2; mt++)
                #pragma unroll
                for (int nt = 0; nt < 4; nt++) {
                    mma_bf16(acc[mt][nt], ah[mt], bh[nt]);
                    mma_bf16(acc[mt][nt], ah[mt], bl[nt]);
                    mma_bf16(acc[mt][nt], al[mt], bh[nt]);
                }
        }
        if ((g & 3) == 3) {
            // tile epilogue
            int combo = combo0 + (g >> 2);
            int n = combo >> 3, p0 = (combo & 7) * 128;
            float* On = out + (size_t)n * (CH*HW);
            int rg = lane >> 2, cg = (lane & 3)*2;
            #pragma unroll
            for (int mt = 0; mt < 2; mt++) {
                int d = d0 + wm*32 + mt*16 + rg;
                float b0 = g_bias[d], b1 = g_bias[d+8];
                #pragma unroll
                for (int nt = 0; nt < 4; nt++) {
                    int p = p0 + wn*32 + nt*8 + cg;
                    *(float2*)(On + (size_t)d*HW + p)     = make_float2(acc[mt][nt][0]-b0, acc[mt][nt][1]-b0);
                    *(float2*)(On + (size_t)(d+8)*HW + p) = make_float2(acc[mt][nt][2]-b1, acc[mt][nt][3]-b1);
                }
            }
            #pragma unroll
            for (int a = 0; a < 2; a++)
                #pragma unroll
                for (int b = 0; b < 4; b++)
                    #pragma unroll
                    for (int k = 0; k < 4; k++) acc[a][b][k] = 0.f;
        }
        __syncthreads();
    }
}

// ---------------- launch ----------------
extern "C" void kernel_launch(void* const* d_in, const int* in_sizes, int n_in,
                              void* d_out, int out_size) {
    const float* X   = (const float*)d_in[0];
    const float* rot = (const float*)d_in[1];
    if (n_in >= 2 && in_sizes[0] == CH*CH && in_sizes[1] != CH*CH) {
        X = (const float*)d_in[1]; rot = (const float*)d_in[0];
    }
    float* out = (float*)d_out;
    (void)out_size;

    cudaFuncSetAttribute(k_gram_mma, cudaFuncAttributeMaxDynamicSharedMemorySize, GRAM_SMEM);
    cudaFuncSetAttribute(k_out_mma,  cudaFuncAttributeMaxDynamicSharedMemorySize, OUT_SMEM);
    cudaFuncSetAttribute(k_solver,   cudaFuncAttributeMaxDynamicSharedMemorySize, SOLVER_SMEM);

    k_conv1<<<dim3(256, 64), 256>>>(X);
    k_gram_mma<<<dim3(3, 64), 512, GRAM_SMEM>>>();
    k_solver<<<NCTA, 256, SOLVER_SMEM>>>(rot);
    k_out_mma<<<128, 512, OUT_SMEM>>>(out);
}